// round 13
// baseline (speedup 1.0000x reference)
#include <cuda_runtime.h>
#include <cuda_bf16.h>
#include <math.h>
#include <stdint.h>

// Problem constants
#define BB 2
#define CC 256
#define HH 120
#define WW 240
#define SS (HH*WW)          // 28800
#define HID 512
#define K1 512              // GEMM1 K: [x | hilbert(x)]
#define NROWS (BB*CC*HH)    // 61440 spatial rows of length 240

typedef __nv_bfloat16 bf16;

// ---------------------------------------------------------------------------
// Static scratch
// ---------------------------------------------------------------------------
__device__ bf16  g_xr  [(size_t)BB*CC*SS];     // bf16 copy of x
__device__ bf16  g_hx  [(size_t)BB*CC*SS];     // hilbert(x), bf16
__device__ bf16  g_t0  [(size_t)BB*CC*SS];     // post GEMM1+GELU
__device__ bf16  g_u   [(size_t)BB*HID*SS];    // post mlp1+GELU
__device__ bf16  g_at1 [BB*K1*CC];             // GEMM1 AT [b][k=512][m=256]
__device__ bf16  g_at2 [BB*CC*HID];            // mlp1  AT [b][k=256][m=512]
__device__ bf16  g_w2t [HID*CC];               // mlp2  AT [k=512][m=256]
__device__ bf16  g_ac  [WW*WW];                // circulant Hilbert matrix [w][w']
__device__ float g_bias1[BB*CC];
__device__ float g_bias2[BB*HID];
__device__ float g_mean0[BB*CC];
__device__ float g_rstd0[BB*CC];
__device__ float g_mean1[BB*CC];
__device__ float g_rstd1[BB*CC];
__device__ float g_s1   [BB*CC];               // t0 row-sum accumulator
__device__ float g_q1   [BB*CC];               // t0 row-sumsq accumulator

// ---------------------------------------------------------------------------
// Circulant Hilbert matrix: Ac[w][w'] = a[(w'-w) mod 240]
// ---------------------------------------------------------------------------
__global__ void gen_ac() {
    int idx = blockIdx.x * blockDim.x + threadIdx.x;
    if (idx >= WW * WW) return;
    int w = idx / WW, wp = idx % WW;
    int d = wp - w; if (d < 0) d += WW;
    float v = 0.f;
    if (d & 1) {
        float ang = (float)d * (1.0f / 240.0f);
        v = -(1.0f / 120.0f) * (cospif(ang) / sinpif(ang));
    }
    g_ac[idx] = __float2bfloat16_rn(v);
}

// ---------------------------------------------------------------------------
// InstanceNorm0 statistics (one block per (b,c)); emits bf16 copy of x and
// zeroes the inorm1 accumulators for this bc.
// ---------------------------------------------------------------------------
__global__ void inorm_stats_f32(const float* __restrict__ x,
                                float* __restrict__ mean, float* __restrict__ rstd,
                                bf16* __restrict__ xr) {
    __shared__ float ssum[8];
    __shared__ float ssq[8];
    int bc = blockIdx.x;
    const float4* p = (const float4*)(x + (size_t)bc * SS);
    __nv_bfloat162* pr = (__nv_bfloat162*)(xr + (size_t)bc * SS);
    int t = threadIdx.x;
    float s = 0.f, q = 0.f;
    for (int i = t; i < SS / 4; i += 256) {
        float4 v = p[i];
        s += v.x + v.y + v.z + v.w;
        q += v.x * v.x + v.y * v.y + v.z * v.z + v.w * v.w;
        pr[2 * i]     = __floats2bfloat162_rn(v.x, v.y);
        pr[2 * i + 1] = __floats2bfloat162_rn(v.z, v.w);
    }
    #pragma unroll
    for (int off = 16; off > 0; off >>= 1) {
        s += __shfl_xor_sync(0xffffffffu, s, off);
        q += __shfl_xor_sync(0xffffffffu, q, off);
    }
    int w = t >> 5, l = t & 31;
    if (l == 0) { ssum[w] = s; ssq[w] = q; }
    __syncthreads();
    if (t == 0) {
        float S = 0.f, Q = 0.f;
        #pragma unroll
        for (int i = 0; i < 8; i++) { S += ssum[i]; Q += ssq[i]; }
        float m = S * (1.0f / SS);
        float var = Q * (1.0f / SS) - m * m;
        mean[bc] = m;
        rstd[bc] = rsqrtf(var + 1e-5f);
        g_s1[bc] = 0.f;
        g_q1[bc] = 0.f;
    }
}

// Finalize inorm1 stats from the GEMM1-epilogue accumulators
__global__ void finalize_stats() {
    int bc = blockIdx.x * blockDim.x + threadIdx.x;
    if (bc >= BB * CC) return;
    float m = g_s1[bc] * (1.0f / SS);
    float var = g_q1[bc] * (1.0f / SS) - m * m;
    g_mean1[bc] = m;
    g_rstd1[bc] = rsqrtf(var + 1e-5f);
}

// ---------------------------------------------------------------------------
// ldmatrix / mma primitives
// ---------------------------------------------------------------------------
#define LDSM_X4(r0, r1, r2, r3, addr) \
    asm volatile("ldmatrix.sync.aligned.m8n8.x4.shared.b16 {%0,%1,%2,%3}, [%4];" \
        : "=r"(r0), "=r"(r1), "=r"(r2), "=r"(r3) : "r"(addr))

#define LDSM_X4_T(r0, r1, r2, r3, addr) \
    asm volatile("ldmatrix.sync.aligned.m8n8.x4.trans.shared.b16 {%0,%1,%2,%3}, [%4];" \
        : "=r"(r0), "=r"(r1), "=r"(r2), "=r"(r3) : "r"(addr))

__device__ __forceinline__ void mma_bf16(float4& d,
    uint32_t a0, uint32_t a1, uint32_t a2, uint32_t a3,
    uint32_t b0, uint32_t b1) {
    asm volatile(
        "mma.sync.aligned.m16n8k16.row.col.f32.bf16.bf16.f32 "
        "{%0,%1,%2,%3}, {%4,%5,%6,%7}, {%8,%9}, {%0,%1,%2,%3};\n"
        : "+f"(d.x), "+f"(d.y), "+f"(d.z), "+f"(d.w)
        : "r"(a0), "r"(a1), "r"(a2), "r"(a3), "r"(b0), "r"(b1));
}

// ---------------------------------------------------------------------------
// Hilbert as tensor-core GEMM: hx[r, :] = xr[r, :] @ Ac   (per 128-row block)
// ---------------------------------------------------------------------------
__global__ __launch_bounds__(256)
void hilbert_mma() {
    __shared__ bf16 Xs[3][128][24];
    __shared__ bf16 Cs[3][16][248];

    int tid  = threadIdx.x;
    int lane = tid & 31;
    int wid  = tid >> 5;
    int lrow = lane & 7;
    int lmat = lane >> 3;
    int g    = lane >> 2;
    int tg   = lane & 3;
    size_t n0 = (size_t)blockIdx.x * 128;

    float4 acc[30];
    #pragma unroll
    for (int j = 0; j < 30; j++) acc[j] = make_float4(0.f, 0.f, 0.f, 0.f);

    int xrow = tid >> 1, xhalf = tid & 1;

    auto cpTile = [&](int k0, int st) {
        const bf16* gx = g_xr + (n0 + xrow) * WW + k0 + xhalf * 8;
        unsigned dx = (unsigned)__cvta_generic_to_shared(&Xs[st][xrow][xhalf * 8]);
        asm volatile("cp.async.cg.shared.global [%0], [%1], 16;\n" :: "r"(dx), "l"(gx));
        #pragma unroll
        for (int it = 0; it < 2; it++) {
            int idx = tid + it * 256;
            if (idx < 480) {
                int r = idx / 30, s = idx % 30;
                const bf16* ga = g_ac + (size_t)(k0 + r) * WW + s * 8;
                unsigned da = (unsigned)__cvta_generic_to_shared(&Cs[st][r][s * 8]);
                asm volatile("cp.async.cg.shared.global [%0], [%1], 16;\n" :: "r"(da), "l"(ga));
            }
        }
        asm volatile("cp.async.commit_group;\n");
    };

    auto compute = [&](int st) {
        uint32_t a0, a1, a2, a3;
        unsigned pa = (unsigned)__cvta_generic_to_shared(
            &Xs[st][wid * 16 + (lmat & 1) * 8 + lrow][(lmat >> 1) * 8]);
        LDSM_X4(a0, a1, a2, a3, pa);
        #pragma unroll
        for (int jj = 0; jj < 15; jj++) {
            uint32_t b0, b1, b2, b3;
            unsigned pb = (unsigned)__cvta_generic_to_shared(
                &Cs[st][(lmat & 1) * 8 + lrow][jj * 16 + (lmat >> 1) * 8]);
            LDSM_X4_T(b0, b1, b2, b3, pb);
            mma_bf16(acc[2 * jj],     a0, a1, a2, a3, b0, b1);
            mma_bf16(acc[2 * jj + 1], a0, a1, a2, a3, b2, b3);
        }
    };

    cpTile(0, 0);
    cpTile(16, 1);
    for (int t = 0; t < 13; t++) {
        asm volatile("cp.async.wait_group 1;\n");
        __syncthreads();
        compute(t % 3);
        cpTile((t + 2) * 16, (t + 2) % 3);
    }
    asm volatile("cp.async.wait_group 1;\n");
    __syncthreads();
    compute(13 % 3);
    asm volatile("cp.async.wait_group 0;\n");
    __syncthreads();
    compute(14 % 3);

    size_t r0 = n0 + wid * 16 + g;
    size_t r1 = r0 + 8;
    #pragma unroll
    for (int j = 0; j < 30; j++) {
        int n = j * 8 + 2 * tg;
        float4 c = acc[j];
        *(__nv_bfloat162*)&g_hx[r0 * WW + n] = __floats2bfloat162_rn(c.x, c.y);
        *(__nv_bfloat162*)&g_hx[r1 * WW + n] = __floats2bfloat162_rn(c.z, c.w);
    }
}

// ---------------------------------------------------------------------------
// Fold 1: AT1[b][k][o]  (k<256: Wr[k,o]*sc0 + iw[o,k] ; else Wi[k-256,o]*sc0)
// ---------------------------------------------------------------------------
__global__ void fold1(const float* __restrict__ wr, const float* __restrict__ wi,
                      const float* __restrict__ iw, const float* __restrict__ n0w) {
    int idx = blockIdx.x * blockDim.x + threadIdx.x;
    if (idx >= BB * K1 * CC) return;
    int b = idx / (K1 * CC);
    int r = idx % (K1 * CC);
    int k = r / CC;
    int o = r % CC;
    int kk = (k < CC) ? k : k - CC;
    float sc = g_rstd0[b * CC + kk] * n0w[kk];
    float v;
    if (k < CC) v = wr[k * CC + o] * sc + iw[o * CC + k];
    else        v = wi[kk * CC + o] * sc;
    g_at1[idx] = __float2bfloat16_rn(v);
}

// bias1[b][o] = inner_b[o] + sum_k Wr[k,o]*sh0[b,k]
__global__ void fold1_bias(const float* __restrict__ wr, const float* __restrict__ ib,
                           const float* __restrict__ n0w, const float* __restrict__ n0b) {
    __shared__ float sh[CC];
    int b = blockIdx.x;
    int o = threadIdx.x;
    {
        float m = g_mean0[b * CC + o], rs = g_rstd0[b * CC + o];
        sh[o] = n0b[o] - m * rs * n0w[o];
    }
    __syncthreads();
    float s = 0.f;
    #pragma unroll 8
    for (int k = 0; k < CC; k++)
        s += wr[k * CC + o] * sh[k];
    g_bias1[b * CC + o] = ib[o] + s;
}

// ---------------------------------------------------------------------------
// Fold 2 (norm1+FiLM folded inline): AT2[b][k][m] = w1[m,k]*scale[b,k]
// ---------------------------------------------------------------------------
__global__ void fold2(const float* __restrict__ w1,
                      const float* __restrict__ n1w, const float* __restrict__ gamma) {
    int idx = blockIdx.x * blockDim.x + threadIdx.x;
    if (idx >= BB * CC * HID) return;
    int b = idx / (CC * HID);
    int r = idx % (CC * HID);
    int k = r / HID;
    int m = r % HID;
    float scale = g_rstd1[b * CC + k] * n1w[k] * (1.0f + gamma[k]);
    g_at2[idx] = __float2bfloat16_rn(w1[m * CC + k] * scale);
}

// bias2[b][m] = b1[m] + sum_k w1[m,k]*shift[b,k]
__global__ void fold2_bias(const float* __restrict__ w1, const float* __restrict__ b1,
                           const float* __restrict__ n1w, const float* __restrict__ n1b,
                           const float* __restrict__ gamma, const float* __restrict__ beta) {
    int b = blockIdx.y;
    int m = blockIdx.x * 8 + (threadIdx.x >> 5);
    int lane = threadIdx.x & 31;
    float s = 0.f;
    #pragma unroll
    for (int i = 0; i < CC; i += 32) {
        int k = i + lane;
        float mm = g_mean1[b * CC + k], rs = g_rstd1[b * CC + k];
        float shift = (n1b[k] - mm * rs * n1w[k]) * (1.0f + gamma[k]) + beta[k];
        s += w1[m * CC + k] * shift;
    }
    #pragma unroll
    for (int off = 16; off > 0; off >>= 1) s += __shfl_xor_sync(0xffffffffu, s, off);
    if (lane == 0) g_bias2[b * HID + m] = b1[m] + s;
}

// w2t[k][m] = w2[m][k]
__global__ void pack_w2t(const float* __restrict__ w2) {
    int idx = blockIdx.x * blockDim.x + threadIdx.x;
    if (idx >= HID * CC) return;
    int k = idx / CC, m = idx % CC;
    g_w2t[idx] = __float2bfloat16_rn(w2[m * HID + k]);
}

// ---------------------------------------------------------------------------
// Tensor-core GEMM (mma.sync m16n8k16 bf16): C[m,n] = sum_k AT[k,m]*B[k,n]+bias
// 128x128x16 block tile, 8 warps (2x4), warp tile 64x32 = 4x4 mma frags.
// ldmatrix.x4.trans fragment loads. 3-stage cp.async ring.
// B rows from B1 (k<Ksplit) else B2. EPI 1: GELU ; EPI 2: +resid.
// OUTBF: bf16 out. STATS: accumulate per-row sum/sumsq (inorm1 fusion).
// ---------------------------------------------------------------------------
template<int EPI, int OUTBF, int STATS>
__global__ __launch_bounds__(256)
void mgemm(const bf16* __restrict__ AT, long aStride,
           const bf16* __restrict__ B1, long b1Stride,
           const bf16* __restrict__ B2, long b2Stride, int Ksplit,
           const float* __restrict__ bias, int biasStride,
           const float* __restrict__ resid,
           void* __restrict__ C, int M, int N, int K) {
    __shared__ bf16 As[3][16][136];
    __shared__ bf16 Bs[3][16][136];

    int tid  = threadIdx.x;
    int lane = tid & 31;
    int g    = lane >> 2;          // 0..7
    int tg   = lane & 3;           // 0..3
    int lrow = lane & 7;           // ldmatrix row
    int lmat = lane >> 3;          // ldmatrix matrix id
    int wid  = tid >> 5;
    int wm   = wid >> 2;           // 0..1
    int wn   = wid & 3;            // 0..3
    int mBase = wm * 64;
    int nBase = wn * 32;

    int m0 = blockIdx.y * 128;
    int n0 = blockIdx.x * 128;
    int bz = blockIdx.z;

    const bf16* ATp = AT + (size_t)bz * aStride;

    float4 acc[4][4];
    #pragma unroll
    for (int i = 0; i < 4; i++)
        #pragma unroll
        for (int j = 0; j < 4; j++) acc[i][j] = make_float4(0.f, 0.f, 0.f, 0.f);

    int r  = tid >> 4;            // 0..15 (k row)
    int c8 = (tid & 15) * 8;      // col within 128, 8 bf16 = 16B

    auto cpTile = [&](int k0, int st) {
        const bf16* ga = ATp + (size_t)(k0 + r) * M + m0 + c8;
        unsigned da = (unsigned)__cvta_generic_to_shared(&As[st][r][c8]);
        asm volatile("cp.async.cg.shared.global [%0], [%1], 16;\n" :: "r"(da), "l"(ga));
        int k = k0 + r;
        const bf16* gb = (k < Ksplit)
            ? B1 + (size_t)bz * b1Stride + (size_t)k * N + n0 + c8
            : B2 + (size_t)bz * b2Stride + (size_t)(k - Ksplit) * N + n0 + c8;
        unsigned db = (unsigned)__cvta_generic_to_shared(&Bs[st][r][c8]);
        asm volatile("cp.async.cg.shared.global [%0], [%1], 16;\n" :: "r"(db), "l"(gb));
        asm volatile("cp.async.commit_group;\n");
    };

    auto compute = [&](int st) {
        uint32_t a[4][4], b[4][2];
        #pragma unroll
        for (int i = 0; i < 4; i++) {
            unsigned pa = (unsigned)__cvta_generic_to_shared(
                &As[st][(lmat >> 1) * 8 + lrow][mBase + i * 16 + (lmat & 1) * 8]);
            LDSM_X4_T(a[i][0], a[i][1], a[i][2], a[i][3], pa);
        }
        #pragma unroll
        for (int jj = 0; jj < 2; jj++) {
            unsigned pb = (unsigned)__cvta_generic_to_shared(
                &Bs[st][(lmat & 1) * 8 + lrow][nBase + jj * 16 + (lmat >> 1) * 8]);
            LDSM_X4_T(b[2 * jj][0], b[2 * jj][1], b[2 * jj + 1][0], b[2 * jj + 1][1], pb);
        }
        #pragma unroll
        for (int i = 0; i < 4; i++)
            #pragma unroll
            for (int j = 0; j < 4; j++)
                mma_bf16(acc[i][j], a[i][0], a[i][1], a[i][2], a[i][3],
                         b[j][0], b[j][1]);
    };

    int T = K >> 4;
    cpTile(0, 0);
    cpTile(16, 1);
    for (int t = 0; t < T - 2; t++) {
        asm volatile("cp.async.wait_group 1;\n");
        __syncthreads();
        compute(t % 3);
        cpTile((t + 2) * 16, (t + 2) % 3);
    }
    asm volatile("cp.async.wait_group 1;\n");
    __syncthreads();
    compute((T - 2) % 3);
    asm volatile("cp.async.wait_group 0;\n");
    __syncthreads();
    compute((T - 1) % 3);

    // Epilogue
    float* Cf = (float*)C + (size_t)bz * M * N;
    bf16*  Cb = (bf16*)C  + (size_t)bz * M * N;
    float rs[8], rq[8];
    if (STATS) {
        #pragma unroll
        for (int i = 0; i < 8; i++) { rs[i] = 0.f; rq[i] = 0.f; }
    }
    #pragma unroll
    for (int i = 0; i < 4; i++) {
        int mr0 = m0 + mBase + i * 16 + g;
        int mr1 = mr0 + 8;
        float bv0 = bias[bz * biasStride + mr0];
        float bv1 = bias[bz * biasStride + mr1];
        #pragma unroll
        for (int j = 0; j < 4; j++) {
            int n = n0 + nBase + j * 8 + 2 * tg;
            float4 c = acc[i][j];
            float v0 = c.x + bv0, v1 = c.y + bv0;
            float v2 = c.z + bv1, v3 = c.w + bv1;
            if (EPI == 1) {
                v0 = 0.5f * v0 * (1.0f + erff(v0 * 0.70710678118654752f));
                v1 = 0.5f * v1 * (1.0f + erff(v1 * 0.70710678118654752f));
                v2 = 0.5f * v2 * (1.0f + erff(v2 * 0.70710678118654752f));
                v3 = 0.5f * v3 * (1.0f + erff(v3 * 0.70710678118654752f));
            }
            if (EPI == 2) {
                const float* rp = resid + (size_t)bz * M * N;
                float2 r0 = *(const float2*)&rp[(size_t)mr0 * N + n];
                float2 r1 = *(const float2*)&rp[(size_t)mr1 * N + n];
                v0 += r0.x; v1 += r0.y; v2 += r1.x; v3 += r1.y;
            }
            if (STATS) {
                rs[2 * i]     += v0 + v1;
                rq[2 * i]     += v0 * v0 + v1 * v1;
                rs[2 * i + 1] += v2 + v3;
                rq[2 * i + 1] += v2 * v2 + v3 * v3;
            }
            if (OUTBF) {
                *(__nv_bfloat162*)&Cb[(size_t)mr0 * N + n] = __floats2bfloat162_rn(v0, v1);
                *(__nv_bfloat162*)&Cb[(size_t)mr1 * N + n] = __floats2bfloat162_rn(v2, v3);
            } else {
                *(float2*)&Cf[(size_t)mr0 * N + n] = make_float2(v0, v1);
                *(float2*)&Cf[(size_t)mr1 * N + n] = make_float2(v2, v3);
            }
        }
    }
    if (STATS) {
        #pragma unroll
        for (int i = 0; i < 8; i++) {
            float s = rs[i], q = rq[i];
            s += __shfl_xor_sync(0xffffffffu, s, 1);
            q += __shfl_xor_sync(0xffffffffu, q, 1);
            s += __shfl_xor_sync(0xffffffffu, s, 2);
            q += __shfl_xor_sync(0xffffffffu, q, 2);
            if (tg == 0) {
                int m = m0 + mBase + (i >> 1) * 16 + g + (i & 1) * 8;
                atomicAdd(&g_s1[bz * CC + m], s);
                atomicAdd(&g_q1[bz * CC + m], q);
            }
        }
    }
}

// ---------------------------------------------------------------------------
// Launch
// ---------------------------------------------------------------------------
extern "C" void kernel_launch(void* const* d_in, const int* in_sizes, int n_in,
                              void* d_out, int out_size) {
    const float* x      = (const float*)d_in[0];
    const float* gamma  = (const float*)d_in[1];
    const float* beta   = (const float*)d_in[2];
    const float* n0w    = (const float*)d_in[3];
    const float* n0b    = (const float*)d_in[4];
    const float* n1w    = (const float*)d_in[5];
    const float* n1b    = (const float*)d_in[6];
    const float* wr     = (const float*)d_in[7];
    const float* wi     = (const float*)d_in[8];
    const float* innerw = (const float*)d_in[9];
    const float* innerb = (const float*)d_in[10];
    const float* w1     = (const float*)d_in[11];
    const float* b1     = (const float*)d_in[12];
    const float* w2     = (const float*)d_in[13];
    const float* b2     = (const float*)d_in[14];
    float* out = (float*)d_out;

    bf16 *p_xr, *p_hx, *p_t0, *p_u, *p_at1, *p_at2, *p_w2t;
    float *p_b1f, *p_b2f, *p_mean0, *p_rstd0;
    cudaGetSymbolAddress((void**)&p_xr,  g_xr);
    cudaGetSymbolAddress((void**)&p_hx,  g_hx);
    cudaGetSymbolAddress((void**)&p_t0,  g_t0);
    cudaGetSymbolAddress((void**)&p_u,   g_u);
    cudaGetSymbolAddress((void**)&p_at1, g_at1);
    cudaGetSymbolAddress((void**)&p_at2, g_at2);
    cudaGetSymbolAddress((void**)&p_w2t, g_w2t);
    cudaGetSymbolAddress((void**)&p_b1f, g_bias1);
    cudaGetSymbolAddress((void**)&p_b2f, g_bias2);
    cudaGetSymbolAddress((void**)&p_mean0, g_mean0);
    cudaGetSymbolAddress((void**)&p_rstd0, g_rstd0);

    // weight prep + circulant matrix
    pack_w2t<<<(HID * CC + 255) / 256, 256>>>(w2);
    gen_ac<<<(WW * WW + 255) / 256, 256>>>();
    // inorm0 stats + bf16 copy of x (also zeroes inorm1 accumulators)
    inorm_stats_f32<<<BB * CC, 256>>>(x, p_mean0, p_rstd0, p_xr);
    // fold inorm0 into GEMM1 weights + bias
    fold1<<<(BB * K1 * CC + 255) / 256, 256>>>(wr, wi, innerw, n0w);
    fold1_bias<<<BB, 256>>>(wr, innerb, n0w, n0b);
    // hilbert(x) via tensor cores: hx = xr @ Ac
    hilbert_mma<<<NROWS / 128, 256>>>();
    // GEMM1 + GELU + fused inorm1 partial stats: [256 x 512] x [xr ; hx] -> t0
    mgemm<1, 1, 1><<<dim3(SS / 128, CC / 128, BB), 256>>>(
        p_at1, (long)K1 * CC, p_xr, (long)CC * SS, p_hx, (long)CC * SS, CC,
        p_b1f, CC, nullptr, p_t0, CC, SS, K1);
    // finalize inorm1 stats, fold into mlp1
    finalize_stats<<<2, 256>>>();
    fold2<<<(BB * CC * HID + 255) / 256, 256>>>(w1, n1w, gamma);
    fold2_bias<<<dim3(HID / 8, BB), 256>>>(w1, b1, n1w, n1b, gamma, beta);
    // mlp1 + GELU: [512 x 256] x t0 -> u (bf16)
    mgemm<1, 1, 0><<<dim3(SS / 128, HID / 128, BB), 256>>>(
        p_at2, (long)CC * HID, p_t0, (long)CC * SS, p_t0, (long)CC * SS, CC,
        p_b2f, HID, nullptr, p_u, HID, SS, CC);
    // mlp2 + bias + residual: [256 x 512] x u + x -> out (fp32)
    mgemm<2, 0, 0><<<dim3(SS / 128, CC / 128, BB), 256>>>(
        p_w2t, 0L, p_u, (long)HID * SS, p_u, (long)HID * SS, HID,
        b2, 0, x, out, CC, SS, HID);
}

// round 14
// speedup vs baseline: 1.4452x; 1.4452x over previous
#include <cuda_runtime.h>
#include <cuda_bf16.h>
#include <math.h>
#include <stdint.h>

// Problem constants
#define BB 2
#define CC 256
#define HH 120
#define WW 240
#define SS (HH*WW)          // 28800
#define HID 512
#define K1 512              // GEMM1 K: [x | hilbert(x)]
#define NROWS (BB*CC*HH)    // 61440 spatial rows of length 240

typedef __nv_bfloat16 bf16;

// ---------------------------------------------------------------------------
// Static scratch
// ---------------------------------------------------------------------------
__device__ bf16  g_xr  [(size_t)BB*CC*SS];     // bf16 copy of x
__device__ bf16  g_hx  [(size_t)BB*CC*SS];     // hilbert(x), bf16
__device__ bf16  g_t0  [(size_t)BB*CC*SS];     // post GEMM1+GELU
__device__ bf16  g_u   [(size_t)BB*HID*SS];    // post mlp1+GELU
__device__ bf16  g_at1 [BB*K1*CC];             // GEMM1 AT [b][k=512][m=256]
__device__ bf16  g_at2 [BB*CC*HID];            // mlp1  AT [b][k=256][m=512]
__device__ bf16  g_w2t [HID*CC];               // mlp2  AT [k=512][m=256]
__device__ bf16  g_ac  [WW*WW];                // circulant Hilbert matrix [w][w']
__device__ float g_bias1[BB*CC];
__device__ float g_bias2[BB*HID];
__device__ float g_mean0[BB*CC];
__device__ float g_rstd0[BB*CC];
__device__ float g_mean1[BB*CC];
__device__ float g_rstd1[BB*CC];

// ---------------------------------------------------------------------------
// Merged prep: w2t[k][m] = w2[m][k]  AND  circulant Hilbert matrix
// Ac[w][w'] = a[(w'-w) mod 240], a[d] = -(1/120)*cot(pi*d/240) for odd d.
// ---------------------------------------------------------------------------
__global__ void prep_weights(const float* __restrict__ w2) {
    int idx = blockIdx.x * blockDim.x + threadIdx.x;
    if (idx < HID * CC) {
        int k = idx / CC, m = idx % CC;
        g_w2t[idx] = __float2bfloat16_rn(w2[m * HID + k]);
    }
    if (idx < WW * WW) {
        int w = idx / WW, wp = idx % WW;
        int d = wp - w; if (d < 0) d += WW;
        float v = 0.f;
        if (d & 1) {
            float ang = (float)d * (1.0f / 240.0f);
            v = -(1.0f / 120.0f) * (cospif(ang) / sinpif(ang));
        }
        g_ac[idx] = __float2bfloat16_rn(v);
    }
}

// ---------------------------------------------------------------------------
// InstanceNorm statistics (one block per (b,c)) over fp32 input; emit bf16 copy
// ---------------------------------------------------------------------------
__global__ void inorm_stats_f32(const float* __restrict__ x,
                                float* __restrict__ mean, float* __restrict__ rstd,
                                bf16* __restrict__ xr) {
    __shared__ float ssum[8];
    __shared__ float ssq[8];
    int bc = blockIdx.x;
    const float4* p = (const float4*)(x + (size_t)bc * SS);
    __nv_bfloat162* pr = (__nv_bfloat162*)(xr + (size_t)bc * SS);
    int t = threadIdx.x;
    float s = 0.f, q = 0.f;
    for (int i = t; i < SS / 4; i += 256) {
        float4 v = p[i];
        s += v.x + v.y + v.z + v.w;
        q += v.x * v.x + v.y * v.y + v.z * v.z + v.w * v.w;
        pr[2 * i]     = __floats2bfloat162_rn(v.x, v.y);
        pr[2 * i + 1] = __floats2bfloat162_rn(v.z, v.w);
    }
    #pragma unroll
    for (int off = 16; off > 0; off >>= 1) {
        s += __shfl_xor_sync(0xffffffffu, s, off);
        q += __shfl_xor_sync(0xffffffffu, q, off);
    }
    int w = t >> 5, l = t & 31;
    if (l == 0) { ssum[w] = s; ssq[w] = q; }
    __syncthreads();
    if (t == 0) {
        float S = 0.f, Q = 0.f;
        #pragma unroll
        for (int i = 0; i < 8; i++) { S += ssum[i]; Q += ssq[i]; }
        float m = S * (1.0f / SS);
        float var = Q * (1.0f / SS) - m * m;
        mean[bc] = m;
        rstd[bc] = rsqrtf(var + 1e-5f);
    }
}

// Same but over bf16 input (t0), no emit
__global__ void inorm_stats_bf16(const bf16* __restrict__ x,
                                 float* __restrict__ mean, float* __restrict__ rstd) {
    __shared__ float ssum[8];
    __shared__ float ssq[8];
    int bc = blockIdx.x;
    const uint4* p = (const uint4*)(x + (size_t)bc * SS);
    int t = threadIdx.x;
    float s = 0.f, q = 0.f;
    for (int i = t; i < SS / 8; i += 256) {
        uint4 u = p[i];
        const __nv_bfloat162* h = (const __nv_bfloat162*)&u;
        #pragma unroll
        for (int j = 0; j < 4; j++) {
            float2 f = __bfloat1622float2(h[j]);
            s += f.x + f.y;
            q += f.x * f.x + f.y * f.y;
        }
    }
    #pragma unroll
    for (int off = 16; off > 0; off >>= 1) {
        s += __shfl_xor_sync(0xffffffffu, s, off);
        q += __shfl_xor_sync(0xffffffffu, q, off);
    }
    int w = t >> 5, l = t & 31;
    if (l == 0) { ssum[w] = s; ssq[w] = q; }
    __syncthreads();
    if (t == 0) {
        float S = 0.f, Q = 0.f;
        #pragma unroll
        for (int i = 0; i < 8; i++) { S += ssum[i]; Q += ssq[i]; }
        float m = S * (1.0f / SS);
        float var = Q * (1.0f / SS) - m * m;
        mean[bc] = m;
        rstd[bc] = rsqrtf(var + 1e-5f);
    }
}

// ---------------------------------------------------------------------------
// ldmatrix / mma primitives
// ---------------------------------------------------------------------------
#define LDSM_X4(r0, r1, r2, r3, addr) \
    asm volatile("ldmatrix.sync.aligned.m8n8.x4.shared.b16 {%0,%1,%2,%3}, [%4];" \
        : "=r"(r0), "=r"(r1), "=r"(r2), "=r"(r3) : "r"(addr))

#define LDSM_X4_T(r0, r1, r2, r3, addr) \
    asm volatile("ldmatrix.sync.aligned.m8n8.x4.trans.shared.b16 {%0,%1,%2,%3}, [%4];" \
        : "=r"(r0), "=r"(r1), "=r"(r2), "=r"(r3) : "r"(addr))

__device__ __forceinline__ void mma_bf16(float4& d,
    uint32_t a0, uint32_t a1, uint32_t a2, uint32_t a3,
    uint32_t b0, uint32_t b1) {
    asm volatile(
        "mma.sync.aligned.m16n8k16.row.col.f32.bf16.bf16.f32 "
        "{%0,%1,%2,%3}, {%4,%5,%6,%7}, {%8,%9}, {%0,%1,%2,%3};\n"
        : "+f"(d.x), "+f"(d.y), "+f"(d.z), "+f"(d.w)
        : "r"(a0), "r"(a1), "r"(a2), "r"(a3), "r"(b0), "r"(b1));
}

// ---------------------------------------------------------------------------
// Hilbert as tensor-core GEMM: hx[r, :] = xr[r, :] @ Ac   (per 128-row block)
// ---------------------------------------------------------------------------
__global__ __launch_bounds__(256)
void hilbert_mma() {
    __shared__ bf16 Xs[3][128][24];
    __shared__ bf16 Cs[3][16][248];

    int tid  = threadIdx.x;
    int lane = tid & 31;
    int wid  = tid >> 5;
    int lrow = lane & 7;
    int lmat = lane >> 3;
    int g    = lane >> 2;
    int tg   = lane & 3;
    size_t n0 = (size_t)blockIdx.x * 128;

    float4 acc[30];
    #pragma unroll
    for (int j = 0; j < 30; j++) acc[j] = make_float4(0.f, 0.f, 0.f, 0.f);

    int xrow = tid >> 1, xhalf = tid & 1;

    auto cpTile = [&](int k0, int st) {
        const bf16* gx = g_xr + (n0 + xrow) * WW + k0 + xhalf * 8;
        unsigned dx = (unsigned)__cvta_generic_to_shared(&Xs[st][xrow][xhalf * 8]);
        asm volatile("cp.async.cg.shared.global [%0], [%1], 16;\n" :: "r"(dx), "l"(gx));
        #pragma unroll
        for (int it = 0; it < 2; it++) {
            int idx = tid + it * 256;
            if (idx < 480) {
                int r = idx / 30, s = idx % 30;
                const bf16* ga = g_ac + (size_t)(k0 + r) * WW + s * 8;
                unsigned da = (unsigned)__cvta_generic_to_shared(&Cs[st][r][s * 8]);
                asm volatile("cp.async.cg.shared.global [%0], [%1], 16;\n" :: "r"(da), "l"(ga));
            }
        }
        asm volatile("cp.async.commit_group;\n");
    };

    auto compute = [&](int st) {
        uint32_t a0, a1, a2, a3;
        unsigned pa = (unsigned)__cvta_generic_to_shared(
            &Xs[st][wid * 16 + (lmat & 1) * 8 + lrow][(lmat >> 1) * 8]);
        LDSM_X4(a0, a1, a2, a3, pa);
        #pragma unroll
        for (int jj = 0; jj < 15; jj++) {
            uint32_t b0, b1, b2, b3;
            unsigned pb = (unsigned)__cvta_generic_to_shared(
                &Cs[st][(lmat & 1) * 8 + lrow][jj * 16 + (lmat >> 1) * 8]);
            LDSM_X4_T(b0, b1, b2, b3, pb);
            mma_bf16(acc[2 * jj],     a0, a1, a2, a3, b0, b1);
            mma_bf16(acc[2 * jj + 1], a0, a1, a2, a3, b2, b3);
        }
    };

    cpTile(0, 0);
    cpTile(16, 1);
    for (int t = 0; t < 13; t++) {
        asm volatile("cp.async.wait_group 1;\n");
        __syncthreads();
        compute(t % 3);
        cpTile((t + 2) * 16, (t + 2) % 3);
    }
    asm volatile("cp.async.wait_group 1;\n");
    __syncthreads();
    compute(13 % 3);
    asm volatile("cp.async.wait_group 0;\n");
    __syncthreads();
    compute(14 % 3);

    size_t r0 = n0 + wid * 16 + g;
    size_t r1 = r0 + 8;
    #pragma unroll
    for (int j = 0; j < 30; j++) {
        int n = j * 8 + 2 * tg;
        float4 c = acc[j];
        *(__nv_bfloat162*)&g_hx[r0 * WW + n] = __floats2bfloat162_rn(c.x, c.y);
        *(__nv_bfloat162*)&g_hx[r1 * WW + n] = __floats2bfloat162_rn(c.z, c.w);
    }
}

// ---------------------------------------------------------------------------
// Fold 1: AT1[b][k][o]  (k<256: Wr[k,o]*sc0 + iw[o,k] ; else Wi[k-256,o]*sc0)
// ---------------------------------------------------------------------------
__global__ void fold1(const float* __restrict__ wr, const float* __restrict__ wi,
                      const float* __restrict__ iw, const float* __restrict__ n0w) {
    int idx = blockIdx.x * blockDim.x + threadIdx.x;
    if (idx >= BB * K1 * CC) return;
    int b = idx / (K1 * CC);
    int r = idx % (K1 * CC);
    int k = r / CC;
    int o = r % CC;
    int kk = (k < CC) ? k : k - CC;
    float sc = g_rstd0[b * CC + kk] * n0w[kk];
    float v;
    if (k < CC) v = wr[k * CC + o] * sc + iw[o * CC + k];
    else        v = wi[kk * CC + o] * sc;
    g_at1[idx] = __float2bfloat16_rn(v);
}

// bias1[b][o] = inner_b[o] + sum_k Wr[k,o]*sh0[b,k]
__global__ void fold1_bias(const float* __restrict__ wr, const float* __restrict__ ib,
                           const float* __restrict__ n0w, const float* __restrict__ n0b) {
    __shared__ float sh[CC];
    int b = blockIdx.x;
    int o = threadIdx.x;
    {
        float m = g_mean0[b * CC + o], rs = g_rstd0[b * CC + o];
        sh[o] = n0b[o] - m * rs * n0w[o];
    }
    __syncthreads();
    float s = 0.f;
    #pragma unroll 8
    for (int k = 0; k < CC; k++)
        s += wr[k * CC + o] * sh[k];
    g_bias1[b * CC + o] = ib[o] + s;
}

// ---------------------------------------------------------------------------
// Fold 2 (norm1+FiLM folded inline): AT2[b][k][m] = w1[m,k]*scale[b,k]
// ---------------------------------------------------------------------------
__global__ void fold2(const float* __restrict__ w1,
                      const float* __restrict__ n1w, const float* __restrict__ gamma) {
    int idx = blockIdx.x * blockDim.x + threadIdx.x;
    if (idx >= BB * CC * HID) return;
    int b = idx / (CC * HID);
    int r = idx % (CC * HID);
    int k = r / HID;
    int m = r % HID;
    float scale = g_rstd1[b * CC + k] * n1w[k] * (1.0f + gamma[k]);
    g_at2[idx] = __float2bfloat16_rn(w1[m * CC + k] * scale);
}

// bias2[b][m] = b1[m] + sum_k w1[m,k]*shift[b,k]
__global__ void fold2_bias(const float* __restrict__ w1, const float* __restrict__ b1,
                           const float* __restrict__ n1w, const float* __restrict__ n1b,
                           const float* __restrict__ gamma, const float* __restrict__ beta) {
    int b = blockIdx.y;
    int m = blockIdx.x * 8 + (threadIdx.x >> 5);
    int lane = threadIdx.x & 31;
    float s = 0.f;
    #pragma unroll
    for (int i = 0; i < CC; i += 32) {
        int k = i + lane;
        float mm = g_mean1[b * CC + k], rs = g_rstd1[b * CC + k];
        float shift = (n1b[k] - mm * rs * n1w[k]) * (1.0f + gamma[k]) + beta[k];
        s += w1[m * CC + k] * shift;
    }
    #pragma unroll
    for (int off = 16; off > 0; off >>= 1) s += __shfl_xor_sync(0xffffffffu, s, off);
    if (lane == 0) g_bias2[b * HID + m] = b1[m] + s;
}

// ---------------------------------------------------------------------------
// Tensor-core GEMM (mma.sync m16n8k16 bf16): C[m,n] = sum_k AT[k,m]*B[k,n]+bias
// 128x128x16 block tile, 8 warps (2x4), warp tile 64x32 = 4x4 mma frags.
// ldmatrix.x4.trans fragment loads. 3-stage cp.async ring.
// B rows from B1 (k<Ksplit) else B2. EPI 1: GELU ; EPI 2: +resid.
// OUTBF: store bf16, else fp32.
// ---------------------------------------------------------------------------
template<int EPI, int OUTBF>
__global__ __launch_bounds__(256)
void mgemm(const bf16* __restrict__ AT, long aStride,
           const bf16* __restrict__ B1, long b1Stride,
           const bf16* __restrict__ B2, long b2Stride, int Ksplit,
           const float* __restrict__ bias, int biasStride,
           const float* __restrict__ resid,
           void* __restrict__ C, int M, int N, int K) {
    __shared__ bf16 As[3][16][136];
    __shared__ bf16 Bs[3][16][136];

    int tid  = threadIdx.x;
    int lane = tid & 31;
    int g    = lane >> 2;          // 0..7
    int tg   = lane & 3;           // 0..3
    int lrow = lane & 7;           // ldmatrix row
    int lmat = lane >> 3;          // ldmatrix matrix id
    int wid  = tid >> 5;
    int wm   = wid >> 2;           // 0..1
    int wn   = wid & 3;            // 0..3
    int mBase = wm * 64;
    int nBase = wn * 32;

    int m0 = blockIdx.y * 128;
    int n0 = blockIdx.x * 128;
    int bz = blockIdx.z;

    const bf16* ATp = AT + (size_t)bz * aStride;

    float4 acc[4][4];
    #pragma unroll
    for (int i = 0; i < 4; i++)
        #pragma unroll
        for (int j = 0; j < 4; j++) acc[i][j] = make_float4(0.f, 0.f, 0.f, 0.f);

    int r  = tid >> 4;            // 0..15 (k row)
    int c8 = (tid & 15) * 8;      // col within 128, 8 bf16 = 16B

    auto cpTile = [&](int k0, int st) {
        const bf16* ga = ATp + (size_t)(k0 + r) * M + m0 + c8;
        unsigned da = (unsigned)__cvta_generic_to_shared(&As[st][r][c8]);
        asm volatile("cp.async.cg.shared.global [%0], [%1], 16;\n" :: "r"(da), "l"(ga));
        int k = k0 + r;
        const bf16* gb = (k < Ksplit)
            ? B1 + (size_t)bz * b1Stride + (size_t)k * N + n0 + c8
            : B2 + (size_t)bz * b2Stride + (size_t)(k - Ksplit) * N + n0 + c8;
        unsigned db = (unsigned)__cvta_generic_to_shared(&Bs[st][r][c8]);
        asm volatile("cp.async.cg.shared.global [%0], [%1], 16;\n" :: "r"(db), "l"(gb));
        asm volatile("cp.async.commit_group;\n");
    };

    auto compute = [&](int st) {
        uint32_t a[4][4], b[4][2];
        #pragma unroll
        for (int i = 0; i < 4; i++) {
            unsigned pa = (unsigned)__cvta_generic_to_shared(
                &As[st][(lmat >> 1) * 8 + lrow][mBase + i * 16 + (lmat & 1) * 8]);
            LDSM_X4_T(a[i][0], a[i][1], a[i][2], a[i][3], pa);
        }
        #pragma unroll
        for (int jj = 0; jj < 2; jj++) {
            unsigned pb = (unsigned)__cvta_generic_to_shared(
                &Bs[st][(lmat & 1) * 8 + lrow][nBase + jj * 16 + (lmat >> 1) * 8]);
            LDSM_X4_T(b[2 * jj][0], b[2 * jj][1], b[2 * jj + 1][0], b[2 * jj + 1][1], pb);
        }
        #pragma unroll
        for (int i = 0; i < 4; i++)
            #pragma unroll
            for (int j = 0; j < 4; j++)
                mma_bf16(acc[i][j], a[i][0], a[i][1], a[i][2], a[i][3],
                         b[j][0], b[j][1]);
    };

    int T = K >> 4;
    cpTile(0, 0);
    cpTile(16, 1);
    for (int t = 0; t < T - 2; t++) {
        asm volatile("cp.async.wait_group 1;\n");
        __syncthreads();
        compute(t % 3);
        cpTile((t + 2) * 16, (t + 2) % 3);
    }
    asm volatile("cp.async.wait_group 1;\n");
    __syncthreads();
    compute((T - 2) % 3);
    asm volatile("cp.async.wait_group 0;\n");
    __syncthreads();
    compute((T - 1) % 3);

    // Epilogue
    float* Cf = (float*)C + (size_t)bz * M * N;
    bf16*  Cb = (bf16*)C  + (size_t)bz * M * N;
    #pragma unroll
    for (int i = 0; i < 4; i++) {
        int mr0 = m0 + mBase + i * 16 + g;
        int mr1 = mr0 + 8;
        float bv0 = bias[bz * biasStride + mr0];
        float bv1 = bias[bz * biasStride + mr1];
        #pragma unroll
        for (int j = 0; j < 4; j++) {
            int n = n0 + nBase + j * 8 + 2 * tg;
            float4 c = acc[i][j];
            float v0 = c.x + bv0, v1 = c.y + bv0;
            float v2 = c.z + bv1, v3 = c.w + bv1;
            if (EPI == 1) {
                v0 = 0.5f * v0 * (1.0f + erff(v0 * 0.70710678118654752f));
                v1 = 0.5f * v1 * (1.0f + erff(v1 * 0.70710678118654752f));
                v2 = 0.5f * v2 * (1.0f + erff(v2 * 0.70710678118654752f));
                v3 = 0.5f * v3 * (1.0f + erff(v3 * 0.70710678118654752f));
            }
            if (EPI == 2) {
                const float* rp = resid + (size_t)bz * M * N;
                float2 r0 = *(const float2*)&rp[(size_t)mr0 * N + n];
                float2 r1 = *(const float2*)&rp[(size_t)mr1 * N + n];
                v0 += r0.x; v1 += r0.y; v2 += r1.x; v3 += r1.y;
            }
            if (OUTBF) {
                *(__nv_bfloat162*)&Cb[(size_t)mr0 * N + n] = __floats2bfloat162_rn(v0, v1);
                *(__nv_bfloat162*)&Cb[(size_t)mr1 * N + n] = __floats2bfloat162_rn(v2, v3);
            } else {
                *(float2*)&Cf[(size_t)mr0 * N + n] = make_float2(v0, v1);
                *(float2*)&Cf[(size_t)mr1 * N + n] = make_float2(v2, v3);
            }
        }
    }
}

// ---------------------------------------------------------------------------
// Launch
// ---------------------------------------------------------------------------
extern "C" void kernel_launch(void* const* d_in, const int* in_sizes, int n_in,
                              void* d_out, int out_size) {
    const float* x      = (const float*)d_in[0];
    const float* gamma  = (const float*)d_in[1];
    const float* beta   = (const float*)d_in[2];
    const float* n0w    = (const float*)d_in[3];
    const float* n0b    = (const float*)d_in[4];
    const float* n1w    = (const float*)d_in[5];
    const float* n1b    = (const float*)d_in[6];
    const float* wr     = (const float*)d_in[7];
    const float* wi     = (const float*)d_in[8];
    const float* innerw = (const float*)d_in[9];
    const float* innerb = (const float*)d_in[10];
    const float* w1     = (const float*)d_in[11];
    const float* b1     = (const float*)d_in[12];
    const float* w2     = (const float*)d_in[13];
    const float* b2     = (const float*)d_in[14];
    float* out = (float*)d_out;

    bf16 *p_xr, *p_hx, *p_t0, *p_u, *p_at1, *p_at2, *p_w2t;
    float *p_b1f, *p_b2f, *p_mean0, *p_rstd0, *p_mean1, *p_rstd1;
    cudaGetSymbolAddress((void**)&p_xr,  g_xr);
    cudaGetSymbolAddress((void**)&p_hx,  g_hx);
    cudaGetSymbolAddress((void**)&p_t0,  g_t0);
    cudaGetSymbolAddress((void**)&p_u,   g_u);
    cudaGetSymbolAddress((void**)&p_at1, g_at1);
    cudaGetSymbolAddress((void**)&p_at2, g_at2);
    cudaGetSymbolAddress((void**)&p_w2t, g_w2t);
    cudaGetSymbolAddress((void**)&p_b1f, g_bias1);
    cudaGetSymbolAddress((void**)&p_b2f, g_bias2);
    cudaGetSymbolAddress((void**)&p_mean0, g_mean0);
    cudaGetSymbolAddress((void**)&p_rstd0, g_rstd0);
    cudaGetSymbolAddress((void**)&p_mean1, g_mean1);
    cudaGetSymbolAddress((void**)&p_rstd1, g_rstd1);

    // merged weight prep (w2t + circulant matrix)
    prep_weights<<<(HID * CC + 255) / 256, 256>>>(w2);
    // inorm0 stats + bf16 copy of x
    inorm_stats_f32<<<BB * CC, 256>>>(x, p_mean0, p_rstd0, p_xr);
    // fold inorm0 into GEMM1 weights + bias
    fold1<<<(BB * K1 * CC + 255) / 256, 256>>>(wr, wi, innerw, n0w);
    fold1_bias<<<BB, 256>>>(wr, innerb, n0w, n0b);
    // hilbert(x) via tensor cores: hx = xr @ Ac
    hilbert_mma<<<NROWS / 128, 256>>>();
    // GEMM1 + GELU: [256 x 512] x [xr ; hx] -> t0 (bf16)
    mgemm<1, 1><<<dim3(SS / 128, CC / 128, BB), 256>>>(
        p_at1, (long)K1 * CC, p_xr, (long)CC * SS, p_hx, (long)CC * SS, CC,
        p_b1f, CC, nullptr, p_t0, CC, SS, K1);
    // inorm1 stats + affine fold into mlp1
    inorm_stats_bf16<<<BB * CC, 256>>>(p_t0, p_mean1, p_rstd1);
    fold2<<<(BB * CC * HID + 255) / 256, 256>>>(w1, n1w, gamma);
    fold2_bias<<<dim3(HID / 8, BB), 256>>>(w1, b1, n1w, n1b, gamma, beta);
    // mlp1 + GELU: [512 x 256] x t0 -> u (bf16)
    mgemm<1, 1><<<dim3(SS / 128, HID / 128, BB), 256>>>(
        p_at2, (long)CC * HID, p_t0, (long)CC * SS, p_t0, (long)CC * SS, CC,
        p_b2f, HID, nullptr, p_u, HID, SS, CC);
    // mlp2 + bias + residual: [256 x 512] x u + x -> out (fp32)
    mgemm<2, 0><<<dim3(SS / 128, CC / 128, BB), 256>>>(
        p_w2t, 0L, p_u, (long)HID * SS, p_u, (long)HID * SS, HID,
        b2, 0, x, out, CC, SS, HID);
}

// round 15
// speedup vs baseline: 1.4989x; 1.0371x over previous
#include <cuda_runtime.h>
#include <cuda_bf16.h>
#include <math.h>
#include <stdint.h>

// Problem constants
#define BB 2
#define CC 256
#define HH 120
#define WW 240
#define SS (HH*WW)          // 28800
#define HID 512
#define K1 512              // GEMM1 K: [x | hilbert(x)]
#define NROWS (BB*CC*HH)    // 61440 spatial rows of length 240

typedef __nv_bfloat16 bf16;

// ---------------------------------------------------------------------------
// Static scratch
// ---------------------------------------------------------------------------
__device__ bf16  g_xr  [(size_t)BB*CC*SS];     // bf16 copy of x
__device__ bf16  g_hx  [(size_t)BB*CC*SS];     // hilbert(x), bf16
__device__ bf16  g_t0  [(size_t)BB*CC*SS];     // post GEMM1+GELU
__device__ bf16  g_u   [(size_t)BB*HID*SS];    // post mlp1+GELU
__device__ bf16  g_at1 [BB*K1*CC];             // GEMM1 AT [b][k=512][m=256]
__device__ bf16  g_at2 [BB*CC*HID];            // mlp1  AT [b][k=256][m=512]
__device__ bf16  g_w2t [HID*CC];               // mlp2  AT [k=512][m=256]
__device__ bf16  g_ac  [WW*WW];                // circulant Hilbert matrix [w][w']
__device__ float g_bias1[BB*CC];
__device__ float g_bias2[BB*HID];
__device__ float g_mean0[BB*CC];
__device__ float g_rstd0[BB*CC];
__device__ float g_mean1[BB*CC];
__device__ float g_rstd1[BB*CC];

// ---------------------------------------------------------------------------
// Merged prep: w2t[k][m] = w2[m][k]  AND  circulant Hilbert matrix
// Ac[w][w'] = a[(w'-w) mod 240], a[d] = -(1/120)*cot(pi*d/240) for odd d.
// ---------------------------------------------------------------------------
__global__ void prep_weights(const float* __restrict__ w2) {
    int idx = blockIdx.x * blockDim.x + threadIdx.x;
    if (idx < HID * CC) {
        int k = idx / CC, m = idx % CC;
        g_w2t[idx] = __float2bfloat16_rn(w2[m * HID + k]);
    }
    if (idx < WW * WW) {
        int w = idx / WW, wp = idx % WW;
        int d = wp - w; if (d < 0) d += WW;
        float v = 0.f;
        if (d & 1) {
            float ang = (float)d * (1.0f / 240.0f);
            v = -(1.0f / 120.0f) * (cospif(ang) / sinpif(ang));
        }
        g_ac[idx] = __float2bfloat16_rn(v);
    }
}

// ---------------------------------------------------------------------------
// InstanceNorm statistics (one block per (b,c)) over fp32 input; emit bf16 copy
// ---------------------------------------------------------------------------
__global__ void inorm_stats_f32(const float* __restrict__ x,
                                float* __restrict__ mean, float* __restrict__ rstd,
                                bf16* __restrict__ xr) {
    __shared__ float ssum[8];
    __shared__ float ssq[8];
    int bc = blockIdx.x;
    const float4* p = (const float4*)(x + (size_t)bc * SS);
    __nv_bfloat162* pr = (__nv_bfloat162*)(xr + (size_t)bc * SS);
    int t = threadIdx.x;
    float s = 0.f, q = 0.f;
    for (int i = t; i < SS / 4; i += 256) {
        float4 v = p[i];
        s += v.x + v.y + v.z + v.w;
        q += v.x * v.x + v.y * v.y + v.z * v.z + v.w * v.w;
        pr[2 * i]     = __floats2bfloat162_rn(v.x, v.y);
        pr[2 * i + 1] = __floats2bfloat162_rn(v.z, v.w);
    }
    #pragma unroll
    for (int off = 16; off > 0; off >>= 1) {
        s += __shfl_xor_sync(0xffffffffu, s, off);
        q += __shfl_xor_sync(0xffffffffu, q, off);
    }
    int w = t >> 5, l = t & 31;
    if (l == 0) { ssum[w] = s; ssq[w] = q; }
    __syncthreads();
    if (t == 0) {
        float S = 0.f, Q = 0.f;
        #pragma unroll
        for (int i = 0; i < 8; i++) { S += ssum[i]; Q += ssq[i]; }
        float m = S * (1.0f / SS);
        float var = Q * (1.0f / SS) - m * m;
        mean[bc] = m;
        rstd[bc] = rsqrtf(var + 1e-5f);
    }
}

// Same but over bf16 input (t0), no emit
__global__ void inorm_stats_bf16(const bf16* __restrict__ x,
                                 float* __restrict__ mean, float* __restrict__ rstd) {
    __shared__ float ssum[8];
    __shared__ float ssq[8];
    int bc = blockIdx.x;
    const uint4* p = (const uint4*)(x + (size_t)bc * SS);
    int t = threadIdx.x;
    float s = 0.f, q = 0.f;
    for (int i = t; i < SS / 8; i += 256) {
        uint4 u = p[i];
        const __nv_bfloat162* h = (const __nv_bfloat162*)&u;
        #pragma unroll
        for (int j = 0; j < 4; j++) {
            float2 f = __bfloat1622float2(h[j]);
            s += f.x + f.y;
            q += f.x * f.x + f.y * f.y;
        }
    }
    #pragma unroll
    for (int off = 16; off > 0; off >>= 1) {
        s += __shfl_xor_sync(0xffffffffu, s, off);
        q += __shfl_xor_sync(0xffffffffu, q, off);
    }
    int w = t >> 5, l = t & 31;
    if (l == 0) { ssum[w] = s; ssq[w] = q; }
    __syncthreads();
    if (t == 0) {
        float S = 0.f, Q = 0.f;
        #pragma unroll
        for (int i = 0; i < 8; i++) { S += ssum[i]; Q += ssq[i]; }
        float m = S * (1.0f / SS);
        float var = Q * (1.0f / SS) - m * m;
        mean[bc] = m;
        rstd[bc] = rsqrtf(var + 1e-5f);
    }
}

// ---------------------------------------------------------------------------
// ldmatrix / mma primitives
// ---------------------------------------------------------------------------
#define LDSM_X4(r0, r1, r2, r3, addr) \
    asm volatile("ldmatrix.sync.aligned.m8n8.x4.shared.b16 {%0,%1,%2,%3}, [%4];" \
        : "=r"(r0), "=r"(r1), "=r"(r2), "=r"(r3) : "r"(addr))

#define LDSM_X4_T(r0, r1, r2, r3, addr) \
    asm volatile("ldmatrix.sync.aligned.m8n8.x4.trans.shared.b16 {%0,%1,%2,%3}, [%4];" \
        : "=r"(r0), "=r"(r1), "=r"(r2), "=r"(r3) : "r"(addr))

__device__ __forceinline__ void mma_bf16(float4& d,
    uint32_t a0, uint32_t a1, uint32_t a2, uint32_t a3,
    uint32_t b0, uint32_t b1) {
    asm volatile(
        "mma.sync.aligned.m16n8k16.row.col.f32.bf16.bf16.f32 "
        "{%0,%1,%2,%3}, {%4,%5,%6,%7}, {%8,%9}, {%0,%1,%2,%3};\n"
        : "+f"(d.x), "+f"(d.y), "+f"(d.z), "+f"(d.w)
        : "r"(a0), "r"(a1), "r"(a2), "r"(a3), "r"(b0), "r"(b1));
}

// ---------------------------------------------------------------------------
// Hilbert as tensor-core GEMM: hx[r, :] = xr[r, :] @ Ac   (per 128-row block)
// ---------------------------------------------------------------------------
__global__ __launch_bounds__(256)
void hilbert_mma() {
    __shared__ bf16 Xs[3][128][24];
    __shared__ bf16 Cs[3][16][248];

    int tid  = threadIdx.x;
    int lane = tid & 31;
    int wid  = tid >> 5;
    int lrow = lane & 7;
    int lmat = lane >> 3;
    int g    = lane >> 2;
    int tg   = lane & 3;
    size_t n0 = (size_t)blockIdx.x * 128;

    float4 acc[30];
    #pragma unroll
    for (int j = 0; j < 30; j++) acc[j] = make_float4(0.f, 0.f, 0.f, 0.f);

    int xrow = tid >> 1, xhalf = tid & 1;

    auto cpTile = [&](int k0, int st) {
        const bf16* gx = g_xr + (n0 + xrow) * WW + k0 + xhalf * 8;
        unsigned dx = (unsigned)__cvta_generic_to_shared(&Xs[st][xrow][xhalf * 8]);
        asm volatile("cp.async.cg.shared.global [%0], [%1], 16;\n" :: "r"(dx), "l"(gx));
        #pragma unroll
        for (int it = 0; it < 2; it++) {
            int idx = tid + it * 256;
            if (idx < 480) {
                int r = idx / 30, s = idx % 30;
                const bf16* ga = g_ac + (size_t)(k0 + r) * WW + s * 8;
                unsigned da = (unsigned)__cvta_generic_to_shared(&Cs[st][r][s * 8]);
                asm volatile("cp.async.cg.shared.global [%0], [%1], 16;\n" :: "r"(da), "l"(ga));
            }
        }
        asm volatile("cp.async.commit_group;\n");
    };

    auto compute = [&](int st) {
        uint32_t a0, a1, a2, a3;
        unsigned pa = (unsigned)__cvta_generic_to_shared(
            &Xs[st][wid * 16 + (lmat & 1) * 8 + lrow][(lmat >> 1) * 8]);
        LDSM_X4(a0, a1, a2, a3, pa);
        #pragma unroll
        for (int jj = 0; jj < 15; jj++) {
            uint32_t b0, b1, b2, b3;
            unsigned pb = (unsigned)__cvta_generic_to_shared(
                &Cs[st][(lmat & 1) * 8 + lrow][jj * 16 + (lmat >> 1) * 8]);
            LDSM_X4_T(b0, b1, b2, b3, pb);
            mma_bf16(acc[2 * jj],     a0, a1, a2, a3, b0, b1);
            mma_bf16(acc[2 * jj + 1], a0, a1, a2, a3, b2, b3);
        }
    };

    cpTile(0, 0);
    cpTile(16, 1);
    for (int t = 0; t < 13; t++) {
        asm volatile("cp.async.wait_group 1;\n");
        __syncthreads();
        compute(t % 3);
        cpTile((t + 2) * 16, (t + 2) % 3);
    }
    asm volatile("cp.async.wait_group 1;\n");
    __syncthreads();
    compute(13 % 3);
    asm volatile("cp.async.wait_group 0;\n");
    __syncthreads();
    compute(14 % 3);

    size_t r0 = n0 + wid * 16 + g;
    size_t r1 = r0 + 8;
    #pragma unroll
    for (int j = 0; j < 30; j++) {
        int n = j * 8 + 2 * tg;
        float4 c = acc[j];
        *(__nv_bfloat162*)&g_hx[r0 * WW + n] = __floats2bfloat162_rn(c.x, c.y);
        *(__nv_bfloat162*)&g_hx[r1 * WW + n] = __floats2bfloat162_rn(c.z, c.w);
    }
}

// ---------------------------------------------------------------------------
// Fold 1: AT1[b][k][o]  (k<256: Wr[k,o]*sc0 + iw[o,k] ; else Wi[k-256,o]*sc0)
// ---------------------------------------------------------------------------
__global__ void fold1(const float* __restrict__ wr, const float* __restrict__ wi,
                      const float* __restrict__ iw, const float* __restrict__ n0w) {
    int idx = blockIdx.x * blockDim.x + threadIdx.x;
    if (idx >= BB * K1 * CC) return;
    int b = idx / (K1 * CC);
    int r = idx % (K1 * CC);
    int k = r / CC;
    int o = r % CC;
    int kk = (k < CC) ? k : k - CC;
    float sc = g_rstd0[b * CC + kk] * n0w[kk];
    float v;
    if (k < CC) v = wr[k * CC + o] * sc + iw[o * CC + k];
    else        v = wi[kk * CC + o] * sc;
    g_at1[idx] = __float2bfloat16_rn(v);
}

// bias1[b][o] = inner_b[o] + sum_k Wr[k,o]*sh0[b,k]
// one block per (o, b); 256 threads = k; warp-shuffle reduce (round-3 form,
// measured 5.5us vs 24us for the grid=2 serial variant)
__global__ void fold1_bias(const float* __restrict__ wr, const float* __restrict__ ib,
                           const float* __restrict__ n0w, const float* __restrict__ n0b) {
    __shared__ float red[8];
    int o = blockIdx.x, b = blockIdx.y;
    int t = threadIdx.x;
    float m = g_mean0[b * CC + t], rs = g_rstd0[b * CC + t];
    float sh = n0b[t] - m * rs * n0w[t];
    float s = wr[t * CC + o] * sh;
    #pragma unroll
    for (int off = 16; off > 0; off >>= 1) s += __shfl_xor_sync(0xffffffffu, s, off);
    if ((t & 31) == 0) red[t >> 5] = s;
    __syncthreads();
    if (t == 0) {
        float S = 0.f;
        #pragma unroll
        for (int i = 0; i < 8; i++) S += red[i];
        g_bias1[b * CC + o] = ib[o] + S;
    }
}

// ---------------------------------------------------------------------------
// Fold 2 (norm1+FiLM folded inline): AT2[b][k][m] = w1[m,k]*scale[b,k]
// ---------------------------------------------------------------------------
__global__ void fold2(const float* __restrict__ w1,
                      const float* __restrict__ n1w, const float* __restrict__ gamma) {
    int idx = blockIdx.x * blockDim.x + threadIdx.x;
    if (idx >= BB * CC * HID) return;
    int b = idx / (CC * HID);
    int r = idx % (CC * HID);
    int k = r / HID;
    int m = r % HID;
    float scale = g_rstd1[b * CC + k] * n1w[k] * (1.0f + gamma[k]);
    g_at2[idx] = __float2bfloat16_rn(w1[m * CC + k] * scale);
}

// bias2[b][m] = b1[m] + sum_k w1[m,k]*shift[b,k]
__global__ void fold2_bias(const float* __restrict__ w1, const float* __restrict__ b1,
                           const float* __restrict__ n1w, const float* __restrict__ n1b,
                           const float* __restrict__ gamma, const float* __restrict__ beta) {
    int b = blockIdx.y;
    int m = blockIdx.x * 8 + (threadIdx.x >> 5);
    int lane = threadIdx.x & 31;
    float s = 0.f;
    #pragma unroll
    for (int i = 0; i < CC; i += 32) {
        int k = i + lane;
        float mm = g_mean1[b * CC + k], rs = g_rstd1[b * CC + k];
        float shift = (n1b[k] - mm * rs * n1w[k]) * (1.0f + gamma[k]) + beta[k];
        s += w1[m * CC + k] * shift;
    }
    #pragma unroll
    for (int off = 16; off > 0; off >>= 1) s += __shfl_xor_sync(0xffffffffu, s, off);
    if (lane == 0) g_bias2[b * HID + m] = b1[m] + s;
}

// ---------------------------------------------------------------------------
// Tensor-core GEMM (mma.sync m16n8k16 bf16): C[m,n] = sum_k AT[k,m]*B[k,n]+bias
// 128x128x16 block tile, 8 warps (2x4), warp tile 64x32 = 4x4 mma frags.
// ldmatrix.x4.trans fragment loads. 3-stage cp.async ring.
// B rows from B1 (k<Ksplit) else B2. EPI 1: GELU ; EPI 2: +resid.
// OUTBF: store bf16, else fp32.
// ---------------------------------------------------------------------------
template<int EPI, int OUTBF>
__global__ __launch_bounds__(256)
void mgemm(const bf16* __restrict__ AT, long aStride,
           const bf16* __restrict__ B1, long b1Stride,
           const bf16* __restrict__ B2, long b2Stride, int Ksplit,
           const float* __restrict__ bias, int biasStride,
           const float* __restrict__ resid,
           void* __restrict__ C, int M, int N, int K) {
    __shared__ bf16 As[3][16][136];
    __shared__ bf16 Bs[3][16][136];

    int tid  = threadIdx.x;
    int lane = tid & 31;
    int g    = lane >> 2;          // 0..7
    int tg   = lane & 3;           // 0..3
    int lrow = lane & 7;           // ldmatrix row
    int lmat = lane >> 3;          // ldmatrix matrix id
    int wid  = tid >> 5;
    int wm   = wid >> 2;           // 0..1
    int wn   = wid & 3;            // 0..3
    int mBase = wm * 64;
    int nBase = wn * 32;

    int m0 = blockIdx.y * 128;
    int n0 = blockIdx.x * 128;
    int bz = blockIdx.z;

    const bf16* ATp = AT + (size_t)bz * aStride;

    float4 acc[4][4];
    #pragma unroll
    for (int i = 0; i < 4; i++)
        #pragma unroll
        for (int j = 0; j < 4; j++) acc[i][j] = make_float4(0.f, 0.f, 0.f, 0.f);

    int r  = tid >> 4;            // 0..15 (k row)
    int c8 = (tid & 15) * 8;      // col within 128, 8 bf16 = 16B

    auto cpTile = [&](int k0, int st) {
        const bf16* ga = ATp + (size_t)(k0 + r) * M + m0 + c8;
        unsigned da = (unsigned)__cvta_generic_to_shared(&As[st][r][c8]);
        asm volatile("cp.async.cg.shared.global [%0], [%1], 16;\n" :: "r"(da), "l"(ga));
        int k = k0 + r;
        const bf16* gb = (k < Ksplit)
            ? B1 + (size_t)bz * b1Stride + (size_t)k * N + n0 + c8
            : B2 + (size_t)bz * b2Stride + (size_t)(k - Ksplit) * N + n0 + c8;
        unsigned db = (unsigned)__cvta_generic_to_shared(&Bs[st][r][c8]);
        asm volatile("cp.async.cg.shared.global [%0], [%1], 16;\n" :: "r"(db), "l"(gb));
        asm volatile("cp.async.commit_group;\n");
    };

    auto compute = [&](int st) {
        uint32_t a[4][4], b[4][2];
        #pragma unroll
        for (int i = 0; i < 4; i++) {
            unsigned pa = (unsigned)__cvta_generic_to_shared(
                &As[st][(lmat >> 1) * 8 + lrow][mBase + i * 16 + (lmat & 1) * 8]);
            LDSM_X4_T(a[i][0], a[i][1], a[i][2], a[i][3], pa);
        }
        #pragma unroll
        for (int jj = 0; jj < 2; jj++) {
            unsigned pb = (unsigned)__cvta_generic_to_shared(
                &Bs[st][(lmat & 1) * 8 + lrow][nBase + jj * 16 + (lmat >> 1) * 8]);
            LDSM_X4_T(b[2 * jj][0], b[2 * jj][1], b[2 * jj + 1][0], b[2 * jj + 1][1], pb);
        }
        #pragma unroll
        for (int i = 0; i < 4; i++)
            #pragma unroll
            for (int j = 0; j < 4; j++)
                mma_bf16(acc[i][j], a[i][0], a[i][1], a[i][2], a[i][3],
                         b[j][0], b[j][1]);
    };

    int T = K >> 4;
    cpTile(0, 0);
    cpTile(16, 1);
    for (int t = 0; t < T - 2; t++) {
        asm volatile("cp.async.wait_group 1;\n");
        __syncthreads();
        compute(t % 3);
        cpTile((t + 2) * 16, (t + 2) % 3);
    }
    asm volatile("cp.async.wait_group 1;\n");
    __syncthreads();
    compute((T - 2) % 3);
    asm volatile("cp.async.wait_group 0;\n");
    __syncthreads();
    compute((T - 1) % 3);

    // Epilogue
    float* Cf = (float*)C + (size_t)bz * M * N;
    bf16*  Cb = (bf16*)C  + (size_t)bz * M * N;
    #pragma unroll
    for (int i = 0; i < 4; i++) {
        int mr0 = m0 + mBase + i * 16 + g;
        int mr1 = mr0 + 8;
        float bv0 = bias[bz * biasStride + mr0];
        float bv1 = bias[bz * biasStride + mr1];
        #pragma unroll
        for (int j = 0; j < 4; j++) {
            int n = n0 + nBase + j * 8 + 2 * tg;
            float4 c = acc[i][j];
            float v0 = c.x + bv0, v1 = c.y + bv0;
            float v2 = c.z + bv1, v3 = c.w + bv1;
            if (EPI == 1) {
                v0 = 0.5f * v0 * (1.0f + erff(v0 * 0.70710678118654752f));
                v1 = 0.5f * v1 * (1.0f + erff(v1 * 0.70710678118654752f));
                v2 = 0.5f * v2 * (1.0f + erff(v2 * 0.70710678118654752f));
                v3 = 0.5f * v3 * (1.0f + erff(v3 * 0.70710678118654752f));
            }
            if (EPI == 2) {
                const float* rp = resid + (size_t)bz * M * N;
                float2 r0 = *(const float2*)&rp[(size_t)mr0 * N + n];
                float2 r1 = *(const float2*)&rp[(size_t)mr1 * N + n];
                v0 += r0.x; v1 += r0.y; v2 += r1.x; v3 += r1.y;
            }
            if (OUTBF) {
                *(__nv_bfloat162*)&Cb[(size_t)mr0 * N + n] = __floats2bfloat162_rn(v0, v1);
                *(__nv_bfloat162*)&Cb[(size_t)mr1 * N + n] = __floats2bfloat162_rn(v2, v3);
            } else {
                *(float2*)&Cf[(size_t)mr0 * N + n] = make_float2(v0, v1);
                *(float2*)&Cf[(size_t)mr1 * N + n] = make_float2(v2, v3);
            }
        }
    }
}

// ---------------------------------------------------------------------------
// Launch
// ---------------------------------------------------------------------------
extern "C" void kernel_launch(void* const* d_in, const int* in_sizes, int n_in,
                              void* d_out, int out_size) {
    const float* x      = (const float*)d_in[0];
    const float* gamma  = (const float*)d_in[1];
    const float* beta   = (const float*)d_in[2];
    const float* n0w    = (const float*)d_in[3];
    const float* n0b    = (const float*)d_in[4];
    const float* n1w    = (const float*)d_in[5];
    const float* n1b    = (const float*)d_in[6];
    const float* wr     = (const float*)d_in[7];
    const float* wi     = (const float*)d_in[8];
    const float* innerw = (const float*)d_in[9];
    const float* innerb = (const float*)d_in[10];
    const float* w1     = (const float*)d_in[11];
    const float* b1     = (const float*)d_in[12];
    const float* w2     = (const float*)d_in[13];
    const float* b2     = (const float*)d_in[14];
    float* out = (float*)d_out;

    bf16 *p_xr, *p_hx, *p_t0, *p_u, *p_at1, *p_at2, *p_w2t;
    float *p_b1f, *p_b2f, *p_mean0, *p_rstd0, *p_mean1, *p_rstd1;
    cudaGetSymbolAddress((void**)&p_xr,  g_xr);
    cudaGetSymbolAddress((void**)&p_hx,  g_hx);
    cudaGetSymbolAddress((void**)&p_t0,  g_t0);
    cudaGetSymbolAddress((void**)&p_u,   g_u);
    cudaGetSymbolAddress((void**)&p_at1, g_at1);
    cudaGetSymbolAddress((void**)&p_at2, g_at2);
    cudaGetSymbolAddress((void**)&p_w2t, g_w2t);
    cudaGetSymbolAddress((void**)&p_b1f, g_bias1);
    cudaGetSymbolAddress((void**)&p_b2f, g_bias2);
    cudaGetSymbolAddress((void**)&p_mean0, g_mean0);
    cudaGetSymbolAddress((void**)&p_rstd0, g_rstd0);
    cudaGetSymbolAddress((void**)&p_mean1, g_mean1);
    cudaGetSymbolAddress((void**)&p_rstd1, g_rstd1);

    // merged weight prep (w2t + circulant matrix)
    prep_weights<<<(HID * CC + 255) / 256, 256>>>(w2);
    // inorm0 stats + bf16 copy of x
    inorm_stats_f32<<<BB * CC, 256>>>(x, p_mean0, p_rstd0, p_xr);
    // fold inorm0 into GEMM1 weights + bias
    fold1<<<(BB * K1 * CC + 255) / 256, 256>>>(wr, wi, innerw, n0w);
    fold1_bias<<<dim3(CC, BB), 256>>>(wr, innerb, n0w, n0b);
    // hilbert(x) via tensor cores: hx = xr @ Ac
    hilbert_mma<<<NROWS / 128, 256>>>();
    // GEMM1 + GELU: [256 x 512] x [xr ; hx] -> t0 (bf16)
    mgemm<1, 1><<<dim3(SS / 128, CC / 128, BB), 256>>>(
        p_at1, (long)K1 * CC, p_xr, (long)CC * SS, p_hx, (long)CC * SS, CC,
        p_b1f, CC, nullptr, p_t0, CC, SS, K1);
    // inorm1 stats + affine fold into mlp1
    inorm_stats_bf16<<<BB * CC, 256>>>(p_t0, p_mean1, p_rstd1);
    fold2<<<(BB * CC * HID + 255) / 256, 256>>>(w1, n1w, gamma);
    fold2_bias<<<dim3(HID / 8, BB), 256>>>(w1, b1, n1w, n1b, gamma, beta);
    // mlp1 + GELU: [512 x 256] x t0 -> u (bf16)
    mgemm<1, 1><<<dim3(SS / 128, HID / 128, BB), 256>>>(
        p_at2, (long)CC * HID, p_t0, (long)CC * SS, p_t0, (long)CC * SS, CC,
        p_b2f, HID, nullptr, p_u, HID, SS, CC);
    // mlp2 + bias + residual: [256 x 512] x u + x -> out (fp32)
    mgemm<2, 0><<<dim3(SS / 128, CC / 128, BB), 256>>>(
        p_w2t, 0L, p_u, (long)HID * SS, p_u, (long)HID * SS, HID,
        b2, 0, x, out, CC, SS, HID);
}

// round 16
// speedup vs baseline: 1.5672x; 1.0455x over previous
#include <cuda_runtime.h>
#include <cuda_bf16.h>
#include <math.h>
#include <stdint.h>

// Problem constants
#define BB 2
#define CC 256
#define HH 120
#define WW 240
#define SS (HH*WW)          // 28800
#define HID 512
#define K1 512              // GEMM1 K: [x | hilbert(x)]
#define NROWS (BB*CC*HH)    // 61440 spatial rows of length 240

typedef __nv_bfloat16 bf16;

// ---------------------------------------------------------------------------
// Static scratch
// ---------------------------------------------------------------------------
__device__ bf16  g_xr  [(size_t)BB*CC*SS];     // bf16 copy of x
__device__ bf16  g_hx  [(size_t)BB*CC*SS];     // hilbert(x), bf16
__device__ bf16  g_t0  [(size_t)BB*CC*SS];     // post GEMM1+GELU
__device__ bf16  g_u   [(size_t)BB*HID*SS];    // post mlp1+GELU
__device__ bf16  g_at1 [BB*K1*CC];             // GEMM1 AT [b][k=512][m=256]
__device__ bf16  g_at2 [BB*CC*HID];            // mlp1  AT [b][k=256][m=512]
__device__ bf16  g_w2t [HID*CC];               // mlp2  AT [k=512][m=256]
__device__ bf16  g_ac  [WW*WW];                // circulant Hilbert matrix [w][w']
__device__ float g_bias1[BB*CC];
__device__ float g_bias2[BB*HID];
__device__ float g_mean0[BB*CC];
__device__ float g_rstd0[BB*CC];
__device__ float g_mean1[BB*CC];
__device__ float g_rstd1[BB*CC];

// ---------------------------------------------------------------------------
// Merged prep: w2t[k][m] = w2[m][k]  AND  circulant Hilbert matrix
// Ac[w][w'] = a[(w'-w) mod 240], a[d] = -(1/120)*cot(pi*d/240) for odd d.
// ---------------------------------------------------------------------------
__global__ void prep_weights(const float* __restrict__ w2) {
    int idx = blockIdx.x * blockDim.x + threadIdx.x;
    if (idx < HID * CC) {
        int k = idx / CC, m = idx % CC;
        g_w2t[idx] = __float2bfloat16_rn(w2[m * HID + k]);
    }
    if (idx < WW * WW) {
        int w = idx / WW, wp = idx % WW;
        int d = wp - w; if (d < 0) d += WW;
        float v = 0.f;
        if (d & 1) {
            float ang = (float)d * (1.0f / 240.0f);
            v = -(1.0f / 120.0f) * (cospif(ang) / sinpif(ang));
        }
        g_ac[idx] = __float2bfloat16_rn(v);
    }
}

// ---------------------------------------------------------------------------
// InstanceNorm statistics (one block per (b,c)) over fp32 input; emit bf16 copy
// ---------------------------------------------------------------------------
__global__ void inorm_stats_f32(const float* __restrict__ x,
                                float* __restrict__ mean, float* __restrict__ rstd,
                                bf16* __restrict__ xr) {
    __shared__ float ssum[8];
    __shared__ float ssq[8];
    int bc = blockIdx.x;
    const float4* p = (const float4*)(x + (size_t)bc * SS);
    __nv_bfloat162* pr = (__nv_bfloat162*)(xr + (size_t)bc * SS);
    int t = threadIdx.x;
    float s = 0.f, q = 0.f;
    for (int i = t; i < SS / 4; i += 256) {
        float4 v = p[i];
        s += v.x + v.y + v.z + v.w;
        q += v.x * v.x + v.y * v.y + v.z * v.z + v.w * v.w;
        pr[2 * i]     = __floats2bfloat162_rn(v.x, v.y);
        pr[2 * i + 1] = __floats2bfloat162_rn(v.z, v.w);
    }
    #pragma unroll
    for (int off = 16; off > 0; off >>= 1) {
        s += __shfl_xor_sync(0xffffffffu, s, off);
        q += __shfl_xor_sync(0xffffffffu, q, off);
    }
    int w = t >> 5, l = t & 31;
    if (l == 0) { ssum[w] = s; ssq[w] = q; }
    __syncthreads();
    if (t == 0) {
        float S = 0.f, Q = 0.f;
        #pragma unroll
        for (int i = 0; i < 8; i++) { S += ssum[i]; Q += ssq[i]; }
        float m = S * (1.0f / SS);
        float var = Q * (1.0f / SS) - m * m;
        mean[bc] = m;
        rstd[bc] = rsqrtf(var + 1e-5f);
    }
}

// Same but over bf16 input (t0), no emit
__global__ void inorm_stats_bf16(const bf16* __restrict__ x,
                                 float* __restrict__ mean, float* __restrict__ rstd) {
    __shared__ float ssum[8];
    __shared__ float ssq[8];
    int bc = blockIdx.x;
    const uint4* p = (const uint4*)(x + (size_t)bc * SS);
    int t = threadIdx.x;
    float s = 0.f, q = 0.f;
    for (int i = t; i < SS / 8; i += 256) {
        uint4 u = p[i];
        const __nv_bfloat162* h = (const __nv_bfloat162*)&u;
        #pragma unroll
        for (int j = 0; j < 4; j++) {
            float2 f = __bfloat1622float2(h[j]);
            s += f.x + f.y;
            q += f.x * f.x + f.y * f.y;
        }
    }
    #pragma unroll
    for (int off = 16; off > 0; off >>= 1) {
        s += __shfl_xor_sync(0xffffffffu, s, off);
        q += __shfl_xor_sync(0xffffffffu, q, off);
    }
    int w = t >> 5, l = t & 31;
    if (l == 0) { ssum[w] = s; ssq[w] = q; }
    __syncthreads();
    if (t == 0) {
        float S = 0.f, Q = 0.f;
        #pragma unroll
        for (int i = 0; i < 8; i++) { S += ssum[i]; Q += ssq[i]; }
        float m = S * (1.0f / SS);
        float var = Q * (1.0f / SS) - m * m;
        mean[bc] = m;
        rstd[bc] = rsqrtf(var + 1e-5f);
    }
}

// ---------------------------------------------------------------------------
// ldmatrix / mma primitives
// ---------------------------------------------------------------------------
#define LDSM_X4(r0, r1, r2, r3, addr) \
    asm volatile("ldmatrix.sync.aligned.m8n8.x4.shared.b16 {%0,%1,%2,%3}, [%4];" \
        : "=r"(r0), "=r"(r1), "=r"(r2), "=r"(r3) : "r"(addr))

#define LDSM_X4_T(r0, r1, r2, r3, addr) \
    asm volatile("ldmatrix.sync.aligned.m8n8.x4.trans.shared.b16 {%0,%1,%2,%3}, [%4];" \
        : "=r"(r0), "=r"(r1), "=r"(r2), "=r"(r3) : "r"(addr))

__device__ __forceinline__ void mma_bf16(float4& d,
    uint32_t a0, uint32_t a1, uint32_t a2, uint32_t a3,
    uint32_t b0, uint32_t b1) {
    asm volatile(
        "mma.sync.aligned.m16n8k16.row.col.f32.bf16.bf16.f32 "
        "{%0,%1,%2,%3}, {%4,%5,%6,%7}, {%8,%9}, {%0,%1,%2,%3};\n"
        : "+f"(d.x), "+f"(d.y), "+f"(d.z), "+f"(d.w)
        : "r"(a0), "r"(a1), "r"(a2), "r"(a3), "r"(b0), "r"(b1));
}

// ---------------------------------------------------------------------------
// Hilbert as tensor-core GEMM: hx[r, :] = xr[r, :] @ Ac   (per 128-row block)
// ---------------------------------------------------------------------------
__global__ __launch_bounds__(256)
void hilbert_mma() {
    __shared__ bf16 Xs[3][128][24];
    __shared__ bf16 Cs[3][16][248];

    int tid  = threadIdx.x;
    int lane = tid & 31;
    int wid  = tid >> 5;
    int lrow = lane & 7;
    int lmat = lane >> 3;
    int g    = lane >> 2;
    int tg   = lane & 3;
    size_t n0 = (size_t)blockIdx.x * 128;

    float4 acc[30];
    #pragma unroll
    for (int j = 0; j < 30; j++) acc[j] = make_float4(0.f, 0.f, 0.f, 0.f);

    int xrow = tid >> 1, xhalf = tid & 1;

    auto cpTile = [&](int k0, int st) {
        const bf16* gx = g_xr + (n0 + xrow) * WW + k0 + xhalf * 8;
        unsigned dx = (unsigned)__cvta_generic_to_shared(&Xs[st][xrow][xhalf * 8]);
        asm volatile("cp.async.cg.shared.global [%0], [%1], 16;\n" :: "r"(dx), "l"(gx));
        #pragma unroll
        for (int it = 0; it < 2; it++) {
            int idx = tid + it * 256;
            if (idx < 480) {
                int r = idx / 30, s = idx % 30;
                const bf16* ga = g_ac + (size_t)(k0 + r) * WW + s * 8;
                unsigned da = (unsigned)__cvta_generic_to_shared(&Cs[st][r][s * 8]);
                asm volatile("cp.async.cg.shared.global [%0], [%1], 16;\n" :: "r"(da), "l"(ga));
            }
        }
        asm volatile("cp.async.commit_group;\n");
    };

    auto compute = [&](int st) {
        uint32_t a0, a1, a2, a3;
        unsigned pa = (unsigned)__cvta_generic_to_shared(
            &Xs[st][wid * 16 + (lmat & 1) * 8 + lrow][(lmat >> 1) * 8]);
        LDSM_X4(a0, a1, a2, a3, pa);
        #pragma unroll
        for (int jj = 0; jj < 15; jj++) {
            uint32_t b0, b1, b2, b3;
            unsigned pb = (unsigned)__cvta_generic_to_shared(
                &Cs[st][(lmat & 1) * 8 + lrow][jj * 16 + (lmat >> 1) * 8]);
            LDSM_X4_T(b0, b1, b2, b3, pb);
            mma_bf16(acc[2 * jj],     a0, a1, a2, a3, b0, b1);
            mma_bf16(acc[2 * jj + 1], a0, a1, a2, a3, b2, b3);
        }
    };

    cpTile(0, 0);
    cpTile(16, 1);
    for (int t = 0; t < 13; t++) {
        asm volatile("cp.async.wait_group 1;\n");
        __syncthreads();
        compute(t % 3);
        cpTile((t + 2) * 16, (t + 2) % 3);
    }
    asm volatile("cp.async.wait_group 1;\n");
    __syncthreads();
    compute(13 % 3);
    asm volatile("cp.async.wait_group 0;\n");
    __syncthreads();
    compute(14 % 3);

    size_t r0 = n0 + wid * 16 + g;
    size_t r1 = r0 + 8;
    #pragma unroll
    for (int j = 0; j < 30; j++) {
        int n = j * 8 + 2 * tg;
        float4 c = acc[j];
        *(__nv_bfloat162*)&g_hx[r0 * WW + n] = __floats2bfloat162_rn(c.x, c.y);
        *(__nv_bfloat162*)&g_hx[r1 * WW + n] = __floats2bfloat162_rn(c.z, c.w);
    }
}

// ---------------------------------------------------------------------------
// Fold 1: AT1[b][k][o]  (k<256: Wr[k,o]*sc0 + iw[o,k] ; else Wi[k-256,o]*sc0)
// ---------------------------------------------------------------------------
__global__ void fold1(const float* __restrict__ wr, const float* __restrict__ wi,
                      const float* __restrict__ iw, const float* __restrict__ n0w) {
    int idx = blockIdx.x * blockDim.x + threadIdx.x;
    if (idx >= BB * K1 * CC) return;
    int b = idx / (K1 * CC);
    int r = idx % (K1 * CC);
    int k = r / CC;
    int o = r % CC;
    int kk = (k < CC) ? k : k - CC;
    float sc = g_rstd0[b * CC + kk] * n0w[kk];
    float v;
    if (k < CC) v = wr[k * CC + o] * sc + iw[o * CC + k];
    else        v = wi[kk * CC + o] * sc;
    g_at1[idx] = __float2bfloat16_rn(v);
}

// bias1[b][o] = inner_b[o] + sum_k Wr[k,o]*sh0[b,k]
__global__ void fold1_bias(const float* __restrict__ wr, const float* __restrict__ ib,
                           const float* __restrict__ n0w, const float* __restrict__ n0b) {
    __shared__ float red[8];
    int o = blockIdx.x, b = blockIdx.y;
    int t = threadIdx.x;
    float m = g_mean0[b * CC + t], rs = g_rstd0[b * CC + t];
    float sh = n0b[t] - m * rs * n0w[t];
    float s = wr[t * CC + o] * sh;
    #pragma unroll
    for (int off = 16; off > 0; off >>= 1) s += __shfl_xor_sync(0xffffffffu, s, off);
    if ((t & 31) == 0) red[t >> 5] = s;
    __syncthreads();
    if (t == 0) {
        float S = 0.f;
        #pragma unroll
        for (int i = 0; i < 8; i++) S += red[i];
        g_bias1[b * CC + o] = ib[o] + S;
    }
}

// ---------------------------------------------------------------------------
// Fold 2 (norm1+FiLM folded inline): AT2[b][k][m] = w1[m,k]*scale[b,k]
// ---------------------------------------------------------------------------
__global__ void fold2(const float* __restrict__ w1,
                      const float* __restrict__ n1w, const float* __restrict__ gamma) {
    int idx = blockIdx.x * blockDim.x + threadIdx.x;
    if (idx >= BB * CC * HID) return;
    int b = idx / (CC * HID);
    int r = idx % (CC * HID);
    int k = r / HID;
    int m = r % HID;
    float scale = g_rstd1[b * CC + k] * n1w[k] * (1.0f + gamma[k]);
    g_at2[idx] = __float2bfloat16_rn(w1[m * CC + k] * scale);
}

// bias2[b][m] = b1[m] + sum_k w1[m,k]*shift[b,k]
__global__ void fold2_bias(const float* __restrict__ w1, const float* __restrict__ b1,
                           const float* __restrict__ n1w, const float* __restrict__ n1b,
                           const float* __restrict__ gamma, const float* __restrict__ beta) {
    int b = blockIdx.y;
    int m = blockIdx.x * 8 + (threadIdx.x >> 5);
    int lane = threadIdx.x & 31;
    float s = 0.f;
    #pragma unroll
    for (int i = 0; i < CC; i += 32) {
        int k = i + lane;
        float mm = g_mean1[b * CC + k], rs = g_rstd1[b * CC + k];
        float shift = (n1b[k] - mm * rs * n1w[k]) * (1.0f + gamma[k]) + beta[k];
        s += w1[m * CC + k] * shift;
    }
    #pragma unroll
    for (int off = 16; off > 0; off >>= 1) s += __shfl_xor_sync(0xffffffffu, s, off);
    if (lane == 0) g_bias2[b * HID + m] = b1[m] + s;
}

// ---------------------------------------------------------------------------
// Tensor-core GEMM (mma.sync m16n8k16 bf16): C[m,n] = sum_k AT[k,m]*B[k,n]+bias
// 128x128x16 block tile, 8 warps (2x4), warp tile 64x32 = 4x4 mma frags.
// ldmatrix.x4.trans fragment loads. 4-stage cp.async ring (static smem),
// two chunks kept in flight beyond the consumed one (wait_group 2).
// B rows from B1 (k<Ksplit) else B2. EPI 1: GELU ; EPI 2: +resid.
// OUTBF: store bf16, else fp32.
// ---------------------------------------------------------------------------
template<int EPI, int OUTBF>
__global__ __launch_bounds__(256)
void mgemm(const bf16* __restrict__ AT, long aStride,
           const bf16* __restrict__ B1, long b1Stride,
           const bf16* __restrict__ B2, long b2Stride, int Ksplit,
           const float* __restrict__ bias, int biasStride,
           const float* __restrict__ resid,
           void* __restrict__ C, int M, int N, int K) {
    __shared__ bf16 As[4][16][136];
    __shared__ bf16 Bs[4][16][136];

    int tid  = threadIdx.x;
    int lane = tid & 31;
    int g    = lane >> 2;          // 0..7
    int tg   = lane & 3;           // 0..3
    int lrow = lane & 7;           // ldmatrix row
    int lmat = lane >> 3;          // ldmatrix matrix id
    int wid  = tid >> 5;
    int wm   = wid >> 2;           // 0..1
    int wn   = wid & 3;            // 0..3
    int mBase = wm * 64;
    int nBase = wn * 32;

    int m0 = blockIdx.y * 128;
    int n0 = blockIdx.x * 128;
    int bz = blockIdx.z;

    const bf16* ATp = AT + (size_t)bz * aStride;

    float4 acc[4][4];
    #pragma unroll
    for (int i = 0; i < 4; i++)
        #pragma unroll
        for (int j = 0; j < 4; j++) acc[i][j] = make_float4(0.f, 0.f, 0.f, 0.f);

    int r  = tid >> 4;            // 0..15 (k row)
    int c8 = (tid & 15) * 8;      // col within 128, 8 bf16 = 16B

    auto cpTile = [&](int k0, int st) {
        const bf16* ga = ATp + (size_t)(k0 + r) * M + m0 + c8;
        unsigned da = (unsigned)__cvta_generic_to_shared(&As[st][r][c8]);
        asm volatile("cp.async.cg.shared.global [%0], [%1], 16;\n" :: "r"(da), "l"(ga));
        int k = k0 + r;
        const bf16* gb = (k < Ksplit)
            ? B1 + (size_t)bz * b1Stride + (size_t)k * N + n0 + c8
            : B2 + (size_t)bz * b2Stride + (size_t)(k - Ksplit) * N + n0 + c8;
        unsigned db = (unsigned)__cvta_generic_to_shared(&Bs[st][r][c8]);
        asm volatile("cp.async.cg.shared.global [%0], [%1], 16;\n" :: "r"(db), "l"(gb));
        asm volatile("cp.async.commit_group;\n");
    };

    auto compute = [&](int st) {
        uint32_t a[4][4], b[4][2];
        #pragma unroll
        for (int i = 0; i < 4; i++) {
            unsigned pa = (unsigned)__cvta_generic_to_shared(
                &As[st][(lmat >> 1) * 8 + lrow][mBase + i * 16 + (lmat & 1) * 8]);
            LDSM_X4_T(a[i][0], a[i][1], a[i][2], a[i][3], pa);
        }
        #pragma unroll
        for (int jj = 0; jj < 2; jj++) {
            unsigned pb = (unsigned)__cvta_generic_to_shared(
                &Bs[st][(lmat & 1) * 8 + lrow][nBase + jj * 16 + (lmat >> 1) * 8]);
            LDSM_X4_T(b[2 * jj][0], b[2 * jj][1], b[2 * jj + 1][0], b[2 * jj + 1][1], pb);
        }
        #pragma unroll
        for (int i = 0; i < 4; i++)
            #pragma unroll
            for (int j = 0; j < 4; j++)
                mma_bf16(acc[i][j], a[i][0], a[i][1], a[i][2], a[i][3],
                         b[j][0], b[j][1]);
    };

    int T = K >> 4;                // 32, 16, or 32 — all > 3
    cpTile(0, 0);
    cpTile(16, 1);
    cpTile(32, 2);
    for (int t = 0; t < T - 3; t++) {
        asm volatile("cp.async.wait_group 2;\n");
        __syncthreads();
        compute(t & 3);
        cpTile((t + 3) * 16, (t + 3) & 3);
    }
    asm volatile("cp.async.wait_group 2;\n");
    __syncthreads();
    compute((T - 3) & 3);
    asm volatile("cp.async.wait_group 1;\n");
    __syncthreads();
    compute((T - 2) & 3);
    asm volatile("cp.async.wait_group 0;\n");
    __syncthreads();
    compute((T - 1) & 3);

    // Epilogue
    float* Cf = (float*)C + (size_t)bz * M * N;
    bf16*  Cb = (bf16*)C  + (size_t)bz * M * N;
    #pragma unroll
    for (int i = 0; i < 4; i++) {
        int mr0 = m0 + mBase + i * 16 + g;
        int mr1 = mr0 + 8;
        float bv0 = bias[bz * biasStride + mr0];
        float bv1 = bias[bz * biasStride + mr1];
        #pragma unroll
        for (int j = 0; j < 4; j++) {
            int n = n0 + nBase + j * 8 + 2 * tg;
            float4 c = acc[i][j];
            float v0 = c.x + bv0, v1 = c.y + bv0;
            float v2 = c.z + bv1, v3 = c.w + bv1;
            if (EPI == 1) {
                v0 = 0.5f * v0 * (1.0f + erff(v0 * 0.70710678118654752f));
                v1 = 0.5f * v1 * (1.0f + erff(v1 * 0.70710678118654752f));
                v2 = 0.5f * v2 * (1.0f + erff(v2 * 0.70710678118654752f));
                v3 = 0.5f * v3 * (1.0f + erff(v3 * 0.70710678118654752f));
            }
            if (EPI == 2) {
                const float* rp = resid + (size_t)bz * M * N;
                float2 r0 = *(const float2*)&rp[(size_t)mr0 * N + n];
                float2 r1 = *(const float2*)&rp[(size_t)mr1 * N + n];
                v0 += r0.x; v1 += r0.y; v2 += r1.x; v3 += r1.y;
            }
            if (OUTBF) {
                *(__nv_bfloat162*)&Cb[(size_t)mr0 * N + n] = __floats2bfloat162_rn(v0, v1);
                *(__nv_bfloat162*)&Cb[(size_t)mr1 * N + n] = __floats2bfloat162_rn(v2, v3);
            } else {
                *(float2*)&Cf[(size_t)mr0 * N + n] = make_float2(v0, v1);
                *(float2*)&Cf[(size_t)mr1 * N + n] = make_float2(v2, v3);
            }
        }
    }
}

// ---------------------------------------------------------------------------
// Launch
// ---------------------------------------------------------------------------
extern "C" void kernel_launch(void* const* d_in, const int* in_sizes, int n_in,
                              void* d_out, int out_size) {
    const float* x      = (const float*)d_in[0];
    const float* gamma  = (const float*)d_in[1];
    const float* beta   = (const float*)d_in[2];
    const float* n0w    = (const float*)d_in[3];
    const float* n0b    = (const float*)d_in[4];
    const float* n1w    = (const float*)d_in[5];
    const float* n1b    = (const float*)d_in[6];
    const float* wr     = (const float*)d_in[7];
    const float* wi     = (const float*)d_in[8];
    const float* innerw = (const float*)d_in[9];
    const float* innerb = (const float*)d_in[10];
    const float* w1     = (const float*)d_in[11];
    const float* b1     = (const float*)d_in[12];
    const float* w2     = (const float*)d_in[13];
    const float* b2     = (const float*)d_in[14];
    float* out = (float*)d_out;

    bf16 *p_xr, *p_hx, *p_t0, *p_u, *p_at1, *p_at2, *p_w2t;
    float *p_b1f, *p_b2f, *p_mean0, *p_rstd0, *p_mean1, *p_rstd1;
    cudaGetSymbolAddress((void**)&p_xr,  g_xr);
    cudaGetSymbolAddress((void**)&p_hx,  g_hx);
    cudaGetSymbolAddress((void**)&p_t0,  g_t0);
    cudaGetSymbolAddress((void**)&p_u,   g_u);
    cudaGetSymbolAddress((void**)&p_at1, g_at1);
    cudaGetSymbolAddress((void**)&p_at2, g_at2);
    cudaGetSymbolAddress((void**)&p_w2t, g_w2t);
    cudaGetSymbolAddress((void**)&p_b1f, g_bias1);
    cudaGetSymbolAddress((void**)&p_b2f, g_bias2);
    cudaGetSymbolAddress((void**)&p_mean0, g_mean0);
    cudaGetSymbolAddress((void**)&p_rstd0, g_rstd0);
    cudaGetSymbolAddress((void**)&p_mean1, g_mean1);
    cudaGetSymbolAddress((void**)&p_rstd1, g_rstd1);

    // merged weight prep (w2t + circulant matrix)
    prep_weights<<<(HID * CC + 255) / 256, 256>>>(w2);
    // inorm0 stats + bf16 copy of x
    inorm_stats_f32<<<BB * CC, 256>>>(x, p_mean0, p_rstd0, p_xr);
    // fold inorm0 into GEMM1 weights + bias
    fold1<<<(BB * K1 * CC + 255) / 256, 256>>>(wr, wi, innerw, n0w);
    fold1_bias<<<dim3(CC, BB), 256>>>(wr, innerb, n0w, n0b);
    // hilbert(x) via tensor cores: hx = xr @ Ac
    hilbert_mma<<<NROWS / 128, 256>>>();
    // GEMM1 + GELU: [256 x 512] x [xr ; hx] -> t0 (bf16)
    mgemm<1, 1><<<dim3(SS / 128, CC / 128, BB), 256>>>(
        p_at1, (long)K1 * CC, p_xr, (long)CC * SS, p_hx, (long)CC * SS, CC,
        p_b1f, CC, nullptr, p_t0, CC, SS, K1);
    // inorm1 stats + affine fold into mlp1
    inorm_stats_bf16<<<BB * CC, 256>>>(p_t0, p_mean1, p_rstd1);
    fold2<<<(BB * CC * HID + 255) / 256, 256>>>(w1, n1w, gamma);
    fold2_bias<<<dim3(HID / 8, BB), 256>>>(w1, b1, n1w, n1b, gamma, beta);
    // mlp1 + GELU: [512 x 256] x t0 -> u (bf16)
    mgemm<1, 1><<<dim3(SS / 128, HID / 128, BB), 256>>>(
        p_at2, (long)CC * HID, p_t0, (long)CC * SS, p_t0, (long)CC * SS, CC,
        p_b2f, HID, nullptr, p_u, HID, SS, CC);
    // mlp2 + bias + residual: [256 x 512] x u + x -> out (fp32)
    mgemm<2, 0><<<dim3(SS / 128, CC / 128, BB), 256>>>(
        p_w2t, 0L, p_u, (long)HID * SS, p_u, (long)HID * SS, HID,
        b2, 0, x, out, CC, SS, HID);
}